// round 11
// baseline (speedup 1.0000x reference)
#include <cuda_runtime.h>
#include <cuda_bf16.h>
#include <math.h>
#include <cstdint>

#define Nn   50000
#define Ee   800000
#define Ff   32
#define NINVc 128
#define NLc  4
#define Hc   64
#define Gc   2048
#define EPSf 1e-6f
#define NT   (Ee/128)   // 6250 tiles of 128 edges

// ---------------- device scratch (no allocs allowed) ----------------
__device__ __align__(16) float  g_edge_in[Ee*5];
__device__ float  g_u[Ee*3];
__device__ int    g_src[Ee];
__device__ int    g_dst[Ee];
__device__ __align__(16) float  g_s[Nn*Ff];
__device__ __align__(16) float  g_v0[Nn*Ff];
__device__ __align__(16) float  g_v1[Nn*Ff];
__device__ __align__(16) float  g_v2[Nn*Ff];
__device__ float4 g_acc[Nn*Ff];       // {ms, mv0, mv1, mv2}
__device__ float  g_cnt[Nn];
__device__ float  g_xg[Gc*NINVc];
__device__ float  g_gcnt[Gc];
__device__ float  g_xgp[Gc*NINVc];
__device__ float  g_z1[Gc*NINVc];
__device__ float  g_mean1[NINVc], g_rstd1[NINVc], g_mean2[NINVc], g_rstd2[NINVc];

__device__ __forceinline__ float elu1(float x) { return x > 0.f ? x : expm1f(x); }
__device__ __forceinline__ float elu_fast(float x) { return x > 0.f ? x : (__expf(x) - 1.f); }

// warp-level bf16 mma (sm_80+ baseline PTX; works on plain sm_103 target)
__device__ __forceinline__ void mma16816(float* d, const uint32_t* a, const uint32_t* b) {
    asm volatile(
        "mma.sync.aligned.m16n8k16.row.col.f32.bf16.bf16.f32 "
        "{%0,%1,%2,%3}, {%4,%5,%6,%7}, {%8,%9}, {%0,%1,%2,%3};"
        : "+f"(d[0]), "+f"(d[1]), "+f"(d[2]), "+f"(d[3])
        : "r"(a[0]), "r"(a[1]), "r"(a[2]), "r"(a[3]), "r"(b[0]), "r"(b[1]));
}
__device__ __forceinline__ void bf16split(float x, uint16_t& h, uint16_t& l) {
    __nv_bfloat16 hb = __float2bfloat16_rn(x);
    float r = x - __bfloat162float(hb);
    __nv_bfloat16 lb = __float2bfloat16_rn(r);
    h = __bfloat16_as_ushort(hb);
    l = __bfloat16_as_ushort(lb);
}

// ---------------- zero / preprocessing ----------------
__global__ void k_zero_all() {
    int i = blockIdx.x*blockDim.x + threadIdx.x;
    if (i < Nn*Ff) { g_acc[i] = make_float4(0.f,0.f,0.f,0.f); return; }
    i -= Nn*Ff;
    if (i < Nn) { g_cnt[i] = 0.f; return; }
    i -= Nn;
    if (i < Gc) { g_gcnt[i] = 0.f; return; }
    i -= Gc;
    if (i < Gc*NINVc) g_xg[i] = 0.f;
}
__global__ void k_edge_prep(const float* __restrict__ pos,
                            const int* __restrict__ ei,
                            const float* __restrict__ eattr) {
    int e = blockIdx.x*blockDim.x + threadIdx.x;
    if (e >= Ee) return;
    int src = ei[e];
    int dst = ei[Ee + e];
    float dx = pos[dst*3+0] - pos[src*3+0];
    float dy = pos[dst*3+1] - pos[src*3+1];
    float dz = pos[dst*3+2] - pos[src*3+2];
    float d  = sqrtf(dx*dx + dy*dy + dz*dz + EPSf);
    float inv = 1.0f/d;
    g_edge_in[e*5+0] = d;
    g_edge_in[e*5+1] = eattr[e*4+0];
    g_edge_in[e*5+2] = eattr[e*4+1];
    g_edge_in[e*5+3] = eattr[e*4+2];
    g_edge_in[e*5+4] = eattr[e*4+3];
    g_u[e*3+0] = dx*inv;
    g_u[e*3+1] = dy*inv;
    g_u[e*3+2] = dz*inv;
    g_src[e] = src;
    g_dst[e] = dst;
    atomicAdd(&g_cnt[dst], 1.f);
}
__global__ void k_gcnt(const int* __restrict__ batch) {
    int n = blockIdx.x*blockDim.x + threadIdx.x;
    if (n < Nn) atomicAdd(&g_gcnt[batch[n]], 1.f);
}
__global__ void k_embed(const float* __restrict__ x, const float* __restrict__ pos,
                        const float* __restrict__ W_es, const float* __restrict__ b_es,
                        const float* __restrict__ W_ev) {
    int idx = blockIdx.x*blockDim.x + threadIdx.x;
    if (idx >= Nn*Ff) return;
    int n = idx >> 5, f = idx & 31;
    const float* xr = x + n*5;
    float s = b_es[f], ev = 0.f;
    #pragma unroll
    for (int k = 0; k < 5; k++) {
        float xv = xr[k];
        s  += xv * W_es[k*Ff + f];
        ev += xv * W_ev[k*Ff + f];
    }
    g_s[idx] = s;
    float p0 = pos[n*3+0], p1 = pos[n*3+1], p2 = pos[n*3+2];
    g_v0[idx] = ev*p0;
    g_v1[idx] = ev*p1;
    g_v2[idx] = ev*p2;
}

// ---------------- HMMA fused message kernel ----------------
// Tile = 128 edges, 256 threads (8 warps). Warp w: edges [w*16, w*16+16), N=96 (12 nt).
// Fragment-direct MLP1 (warps partition edges -> computed exactly once, no A smem).
// B packed in FRAGMENT ORDER as uint4 {hi_k2, hi_k2+4, lo_k2, lo_k2+4}:
//   one LDS.128 per (ks, nt) per lane (48 total vs 192 LDS.32).
#define OFF_BP   0          // uint4[4ks][12nt][32lanes] = 24576 B
#define OFF_EINS 24576      // 640 f
#define OFF_US   27136      // 384 f
#define OFF_SRC  28672      // 128 i
#define OFF_DST  29184      // 128 i
#define OFF_W1S  29696      // 320 f
#define OFF_B1S  30976      // 64 f
#define OFF_B2S  31232      // 96 f
#define TC_SMEM  31616
__global__ void __launch_bounds__(256, 2)
k_msg_mma(const float* __restrict__ W1, const float* __restrict__ b1,
          const float* __restrict__ W2, const float* __restrict__ b2) {
    extern __shared__ char smc[];
    uint4* BP   = (uint4*)(smc + OFF_BP);
    float* eins = (float*)(smc + OFF_EINS);
    float* us   = (float*)(smc + OFF_US);
    int* srcs   = (int*)(smc + OFF_SRC);
    int* dsts   = (int*)(smc + OFF_DST);
    float* w1s  = (float*)(smc + OFF_W1S);
    float* b1s  = (float*)(smc + OFF_B1S);
    float* b2s  = (float*)(smc + OFF_B2S);

    int tid = threadIdx.x;
    // stage weights once per block
    for (int i = tid; i < 320; i += 256) w1s[i] = W1[i];
    for (int i = tid; i < 64;  i += 256) b1s[i] = b1[i];
    for (int i = tid; i < 96;  i += 256) b2s[i] = b2[i];
    // pack B = W2^T hi/lo in fragment order
    for (int pk = tid; pk < 4*12*32; pk += 256) {
        int ks = pk / 384;
        int rem = pk - ks*384;
        int nt = rem >> 5;
        int ln = rem & 31;
        int rr = ln >> 2, qq = ln & 3;
        int n = nt*8 + rr;
        int k2 = ks*8 + qq;
        uint16_t h0,l0,h1,l1,h2,l2,h3,l3;
        bf16split(W2[(2*k2  )*96 + n], h0, l0);
        bf16split(W2[(2*k2+1)*96 + n], h1, l1);
        bf16split(W2[(2*k2+8)*96 + n], h2, l2);
        bf16split(W2[(2*k2+9)*96 + n], h3, l3);
        uint4 v;
        v.x = ((uint32_t)h1 << 16) | h0;   // hi @ k-u32 k2
        v.y = ((uint32_t)h3 << 16) | h2;   // hi @ k-u32 k2+4
        v.z = ((uint32_t)l1 << 16) | l0;   // lo @ k2
        v.w = ((uint32_t)l3 << 16) | l2;   // lo @ k2+4
        BP[pk] = v;
    }

    int lane = tid & 31, warp = tid >> 5;
    int m0 = warp * 16;
    int r = lane >> 2, q = lane & 3;

    for (int tile = blockIdx.x; tile < NT; tile += gridDim.x) {
        __syncthreads();   // prior tile smem reads done (weight staging on 1st iter)
        int e0 = tile * 128;
        for (int i = tid; i < 640; i += 256) eins[i] = g_edge_in[e0*5 + i];
        for (int i = tid; i < 384; i += 256) us[i]   = g_u[e0*3 + i];
        if (tid < 128) { srcs[tid] = g_src[e0 + tid]; dsts[tid] = g_dst[e0 + tid]; }
        __syncthreads();

        // per-lane edge inputs for its 2 rows (r, r+8 within warp's 16-edge tile)
        float xv[2][5];
        #pragma unroll
        for (int m = 0; m < 2; m++) {
            int row = m0 + r + m*8;
            #pragma unroll
            for (int i = 0; i < 5; i++) xv[m][i] = eins[row*5 + i];
        }

        // acc init with bias
        float acc[12][4];
        #pragma unroll
        for (int nt = 0; nt < 12; nt++) {
            float2 bb = *(const float2*)&b2s[nt*8 + q*2];
            acc[nt][0] = bb.x; acc[nt][1] = bb.y;
            acc[nt][2] = bb.x; acc[nt][3] = bb.y;
        }

        #pragma unroll
        for (int ks = 0; ks < 4; ks++) {
            // fragment-direct MLP1 for this k-step
            uint32_t ah[4], al[4];
            #pragma unroll
            for (int idx = 0; idx < 2; idx++) {
                int kc = ks*8 + q + idx*4;   // u32 col
                float2 wv[5];
                #pragma unroll
                for (int i = 0; i < 5; i++) wv[i] = *(const float2*)&w1s[i*64 + kc*2];
                float2 bb = *(const float2*)&b1s[kc*2];
                #pragma unroll
                for (int m = 0; m < 2; m++) {
                    float d0 = bb.x, d1 = bb.y;
                    #pragma unroll
                    for (int i = 0; i < 5; i++) {
                        d0 = fmaf(xv[m][i], wv[i].x, d0);
                        d1 = fmaf(xv[m][i], wv[i].y, d1);
                    }
                    d0 = elu_fast(d0); d1 = elu_fast(d1);
                    uint16_t h0,l0,h1,l1;
                    bf16split(d0, h0, l0); bf16split(d1, h1, l1);
                    ah[m + idx*2] = ((uint32_t)h1 << 16) | h0;
                    al[m + idx*2] = ((uint32_t)l1 << 16) | l0;
                }
            }
            // mma over 12 n-tiles; B via one LDS.128 each
            const uint4* bprow = BP + ks*384 + lane;
            #pragma unroll
            for (int nt = 0; nt < 12; nt++) {
                uint4 b = bprow[nt*32];
                uint32_t bh[2] = { b.x, b.y };
                uint32_t bl[2] = { b.z, b.w };
                mma16816(acc[nt], ah, bh);
                mma16816(acc[nt], ah, bl);
                mma16816(acc[nt], al, bh);
            }
        }

        // --- epilogue: messages + RED.128 scatter from fragments ---
        #pragma unroll
        for (int half = 0; half < 2; half++) {
            int e = m0 + r + half*8;
            int src = srcs[e], dst = dsts[e];
            float u0 = us[e*3+0], u1 = us[e*3+1], u2 = us[e*3+2];
            const float* srow = g_s + src*Ff;
            const float* p0r = g_v0 + src*Ff;
            const float* p1r = g_v1 + src*Ff;
            const float* p2r = g_v2 + src*Ff;
            float4* arow = g_acc + dst*Ff;
            #pragma unroll
            for (int nt = 0; nt < 4; nt++) {
                int f = nt*8 + q*2;
                float gs0 = acc[nt  ][half*2+0], gs1 = acc[nt  ][half*2+1];
                float gv0 = acc[nt+4][half*2+0], gv1 = acc[nt+4][half*2+1];
                float gt0 = acc[nt+8][half*2+0], gt1 = acc[nt+8][half*2+1];
                float2 ss = *(const float2*)&srow[f];
                float2 p0 = *(const float2*)&p0r[f];
                float2 p1 = *(const float2*)&p1r[f];
                float2 p2 = *(const float2*)&p2r[f];
                float t0 = gt0*ss.x, t1 = gt1*ss.y;
                atomicAdd(&arow[f],
                    make_float4(gs0*ss.x, fmaf(gv0, p0.x, t0*u0),
                                fmaf(gv0, p1.x, t0*u1), fmaf(gv0, p2.x, t0*u2)));
                atomicAdd(&arow[f+1],
                    make_float4(gs1*ss.y, fmaf(gv1, p0.y, t1*u0),
                                fmaf(gv1, p1.y, t1*u1), fmaf(gv1, p2.y, t1*u2)));
            }
        }
    }
}

// ---------------- per-layer node update: residual s,v + acc reset (invden folded) ----------------
__global__ void k_update(const float* __restrict__ Ws, const float* __restrict__ Wv) {
    __shared__ float  wss[1024], wvs[1024];
    __shared__ float4 msh[4][32];
    int tid = threadIdx.x;
    for (int i = tid; i < 1024; i += 128) { wss[i] = Ws[i]; wvs[i] = Wv[i]; }
    __syncthreads();
    int w = tid >> 5, lane = tid & 31;
    int node = blockIdx.x*4 + w;
    if (node >= Nn) return;
    float invd = 1.f / fmaxf(g_cnt[node], 1.f);
    float4 a = g_acc[node*Ff + lane];
    g_acc[node*Ff + lane] = make_float4(0.f,0.f,0.f,0.f);  // reset for next layer
    msh[w][lane] = make_float4(a.x*invd, a.y*invd, a.z*invd, a.w*invd);
    __syncwarp();
    float so = 0.f, v0 = 0.f, v1 = 0.f, v2 = 0.f;
    #pragma unroll
    for (int f = 0; f < 32; f++) {
        float4 m = msh[w][f];
        float wsv = wss[f*32 + lane];
        float wvv = wvs[f*32 + lane];
        so += m.x*wsv;
        v0 += m.y*wvv; v1 += m.z*wvv; v2 += m.w*wvv;
    }
    int i = node*Ff + lane;
    g_s[i] += elu1(so);
    g_v0[i] += v0; g_v1[i] += v1; g_v2[i] += v2;
}

// ---------------- invariant map + graph pooling (atomic) ----------------
__global__ void k_inv(const float* __restrict__ W_inv, const float* __restrict__ b_inv,
                      const int* __restrict__ batch) {
    __shared__ float wi[64*128];
    __shared__ float bi[128];
    __shared__ float feat[4][64];
    int tid = threadIdx.x;
    for (int i = tid; i < 64*128; i += 128) wi[i] = W_inv[i];
    if (tid < 128) bi[tid] = b_inv[tid];
    __syncthreads();
    int w = tid >> 5, lane = tid & 31;
    int nwarps = gridDim.x*4;
    for (int node = blockIdx.x*4 + w; node < Nn; node += nwarps) {
        int i = node*Ff + lane;
        float sval = g_s[i];
        float a0 = g_v0[i], a1 = g_v1[i], a2 = g_v2[i];
        float vn = sqrtf(a0*a0 + a1*a1 + a2*a2 + EPSf);
        feat[w][lane]      = sval;
        feat[w][32 + lane] = vn;
        __syncwarp();
        int b = batch[node];
        #pragma unroll
        for (int rr = 0; rr < 4; rr++) {
            int c = lane + 32*rr;
            float acc = bi[c];
            #pragma unroll 8
            for (int k = 0; k < 64; k++) acc += feat[w][k] * wi[k*128 + c];
            atomicAdd(&g_xg[b*NINVc + c], acc);
        }
        __syncwarp();
    }
}

// ---------------- head ----------------
__global__ void k_pool_bn1() {
    __shared__ float ssum[256], ssq[256];
    int c = blockIdx.x, tid = threadIdx.x;
    float s = 0.f, q = 0.f;
    for (int g = tid; g < Gc; g += 256) {
        float val = g_xg[g*NINVc + c] / fmaxf(g_gcnt[g], 1.f);
        g_xgp[g*NINVc + c] = val;
        s += val; q += val*val;
    }
    ssum[tid] = s; ssq[tid] = q; __syncthreads();
    for (int st = 128; st > 0; st >>= 1) {
        if (tid < st) { ssum[tid] += ssum[tid+st]; ssq[tid] += ssq[tid+st]; }
        __syncthreads();
    }
    if (tid == 0) {
        float m = ssum[0] / (float)Gc;
        float var = ssq[0] / (float)Gc - m*m;
        g_mean1[c] = m;
        g_rstd1[c] = rsqrtf(var + 1e-5f);
    }
}
__global__ void k_fc1(const float* __restrict__ g1, const float* __restrict__ be1,
                      const float* __restrict__ Wf1, const float* __restrict__ bf1) {
    __shared__ float a[128];
    int g = blockIdx.x, j = threadIdx.x;
    float xv = g_xgp[g*NINVc + j];
    a[j] = elu1((xv - g_mean1[j]) * g_rstd1[j] * g1[j] + be1[j]);
    __syncthreads();
    float acc = bf1[j];
    #pragma unroll 8
    for (int k = 0; k < 128; k++) acc += a[k] * Wf1[k*128 + j];
    g_z1[g*NINVc + j] = acc;
}
__global__ void k_bn2() {
    __shared__ float ssum[256], ssq[256];
    int c = blockIdx.x, tid = threadIdx.x;
    float s = 0.f, q = 0.f;
    for (int g = tid; g < Gc; g += 256) {
        float val = g_z1[g*NINVc + c];
        s += val; q += val*val;
    }
    ssum[tid] = s; ssq[tid] = q; __syncthreads();
    for (int st = 128; st > 0; st >>= 1) {
        if (tid < st) { ssum[tid] += ssum[tid+st]; ssq[tid] += ssq[tid+st]; }
        __syncthreads();
    }
    if (tid == 0) {
        float m = ssum[0] / (float)Gc;
        float var = ssq[0] / (float)Gc - m*m;
        g_mean2[c] = m;
        g_rstd2[c] = rsqrtf(var + 1e-5f);
    }
}
__global__ void k_head(const float* __restrict__ g2, const float* __restrict__ be2,
                       const float* __restrict__ Wf2, const float* __restrict__ bf2,
                       float* __restrict__ out) {
    int w = threadIdx.x >> 5, lane = threadIdx.x & 31;
    int g = blockIdx.x*4 + w;
    if (g >= Gc) return;
    float p = 0.f;
    for (int k = lane; k < 128; k += 32) {
        float zv = g_z1[g*NINVc + k];
        float av = elu1((zv - g_mean2[k]) * g_rstd2[k] * g2[k] + be2[k]);
        p += av * Wf2[k];
    }
    #pragma unroll
    for (int off = 16; off; off >>= 1) p += __shfl_down_sync(0xffffffffu, p, off);
    if (lane == 0) out[g] = p + bf2[0];
}

// ---------------- launch ----------------
extern "C" void kernel_launch(void* const* d_in, const int* in_sizes, int n_in,
                              void* d_out, int out_size) {
    const float* x     = (const float*)d_in[0];
    const float* pos   = (const float*)d_in[1];
    const int*   ei    = (const int*)d_in[2];     // int32 (JAX x64 disabled)
    const float* eattr = (const float*)d_in[3];
    const int*   batch = (const int*)d_in[4];     // int32
    const float* W_es  = (const float*)d_in[5];
    const float* b_es  = (const float*)d_in[6];
    const float* W_ev  = (const float*)d_in[7];
    const float* W1    = (const float*)d_in[8];
    const float* b1    = (const float*)d_in[9];
    const float* W2    = (const float*)d_in[10];
    const float* b2    = (const float*)d_in[11];
    const float* Ws    = (const float*)d_in[12];
    const float* Wv    = (const float*)d_in[13];
    const float* W_inv = (const float*)d_in[14];
    const float* b_inv = (const float*)d_in[15];
    const float* g1    = (const float*)d_in[16];
    const float* be1   = (const float*)d_in[17];
    const float* Wf1   = (const float*)d_in[18];
    const float* bf1   = (const float*)d_in[19];
    const float* g2    = (const float*)d_in[20];
    const float* be2   = (const float*)d_in[21];
    const float* Wf2   = (const float*)d_in[22];
    const float* bf2   = (const float*)d_in[23];
    float* out = (float*)d_out;

    cudaFuncSetAttribute(k_msg_mma, cudaFuncAttributeMaxDynamicSharedMemorySize, TC_SMEM);

    int ztotal = Nn*Ff + Nn + Gc + Gc*NINVc;
    k_zero_all<<<(ztotal + 255)/256, 256>>>();                       // #1
    k_edge_prep<<<(Ee + 255)/256, 256>>>(pos, ei, eattr);            // #2
    k_embed<<<(Nn*Ff + 255)/256, 256>>>(x, pos, W_es, b_es, W_ev);   // #3

    // layer 0 k_msg_mma is launch #4 -> ncu -s 5 -c 1 captures it
    k_msg_mma<<<296, 256, TC_SMEM>>>(W1, b1, W2, b2);                // #4
    k_update<<<Nn/4, 128>>>(Ws, Wv);                                 // #5

    for (int l = 1; l < NLc; l++) {
        k_msg_mma<<<296, 256, TC_SMEM>>>(W1 + l*5*Hc, b1 + l*Hc,
                                         W2 + l*Hc*3*Ff, b2 + l*3*Ff);
        k_update<<<Nn/4, 128>>>(Ws + l*Ff*Ff, Wv + l*Ff*Ff);
    }

    k_gcnt<<<(Nn + 255)/256, 256>>>(batch);
    k_inv<<<1024, 128>>>(W_inv, b_inv, batch);
    k_pool_bn1<<<NINVc, 256>>>();
    k_fc1<<<Gc, 128>>>(g1, be1, Wf1, bf1);
    k_bn2<<<NINVc, 256>>>();
    k_head<<<Gc/4, 128>>>(g2, be2, Wf2, bf2, out);
}

// round 12
// speedup vs baseline: 1.2178x; 1.2178x over previous
#include <cuda_runtime.h>
#include <cuda_bf16.h>
#include <math.h>
#include <cstdint>

#define Nn   50000
#define Ee   800000
#define Ff   32
#define NINVc 128
#define NLc  4
#define Hc   64
#define Gc   2048
#define EPSf 1e-6f
#define NT   (Ee/128)   // 6250 tiles of 128 edges

// ---------------- device scratch (no allocs allowed) ----------------
__device__ __align__(16) float  g_edge_in[Ee*5];
__device__ float  g_u[Ee*3];
__device__ int    g_src[Ee];
__device__ int    g_dst[Ee];
__device__ __align__(16) float  g_s[Nn*Ff];
__device__ __align__(16) float  g_v0[Nn*Ff];
__device__ __align__(16) float  g_v1[Nn*Ff];
__device__ __align__(16) float  g_v2[Nn*Ff];
__device__ float4 g_acc[Nn*Ff];       // {ms, mv0, mv1, mv2}
__device__ float  g_cnt[Nn];
__device__ float  g_xg[Gc*NINVc];
__device__ float  g_gcnt[Gc];
__device__ float  g_xgp[Gc*NINVc];
__device__ float  g_z1[Gc*NINVc];
__device__ float  g_mean1[NINVc], g_rstd1[NINVc], g_mean2[NINVc], g_rstd2[NINVc];

__device__ __forceinline__ float elu1(float x) { return x > 0.f ? x : expm1f(x); }
__device__ __forceinline__ float elu_fast(float x) { return x > 0.f ? x : (__expf(x) - 1.f); }

// warp-level bf16 mma (sm_80+ baseline PTX; works on plain sm_103 target)
__device__ __forceinline__ void mma16816(float* d, const uint32_t* a, const uint32_t* b) {
    asm volatile(
        "mma.sync.aligned.m16n8k16.row.col.f32.bf16.bf16.f32 "
        "{%0,%1,%2,%3}, {%4,%5,%6,%7}, {%8,%9}, {%0,%1,%2,%3};"
        : "+f"(d[0]), "+f"(d[1]), "+f"(d[2]), "+f"(d[3])
        : "r"(a[0]), "r"(a[1]), "r"(a[2]), "r"(a[3]), "r"(b[0]), "r"(b[1]));
}
__device__ __forceinline__ void bf16split(float x, uint16_t& h, uint16_t& l) {
    __nv_bfloat16 hb = __float2bfloat16_rn(x);
    float r = x - __bfloat162float(hb);
    __nv_bfloat16 lb = __float2bfloat16_rn(r);
    h = __bfloat16_as_ushort(hb);
    l = __bfloat16_as_ushort(lb);
}

// ---------------- zero / preprocessing ----------------
__global__ void k_zero_all() {
    int i = blockIdx.x*blockDim.x + threadIdx.x;
    if (i < Nn*Ff) { g_acc[i] = make_float4(0.f,0.f,0.f,0.f); return; }
    i -= Nn*Ff;
    if (i < Nn) { g_cnt[i] = 0.f; return; }
    i -= Nn;
    if (i < Gc) { g_gcnt[i] = 0.f; return; }
    i -= Gc;
    if (i < Gc*NINVc) g_xg[i] = 0.f;
}
__global__ void k_edge_prep(const float* __restrict__ pos,
                            const int* __restrict__ ei,
                            const float* __restrict__ eattr) {
    int e = blockIdx.x*blockDim.x + threadIdx.x;
    if (e >= Ee) return;
    int src = ei[e];
    int dst = ei[Ee + e];
    float dx = pos[dst*3+0] - pos[src*3+0];
    float dy = pos[dst*3+1] - pos[src*3+1];
    float dz = pos[dst*3+2] - pos[src*3+2];
    float d  = sqrtf(dx*dx + dy*dy + dz*dz + EPSf);
    float inv = 1.0f/d;
    g_edge_in[e*5+0] = d;
    g_edge_in[e*5+1] = eattr[e*4+0];
    g_edge_in[e*5+2] = eattr[e*4+1];
    g_edge_in[e*5+3] = eattr[e*4+2];
    g_edge_in[e*5+4] = eattr[e*4+3];
    g_u[e*3+0] = dx*inv;
    g_u[e*3+1] = dy*inv;
    g_u[e*3+2] = dz*inv;
    g_src[e] = src;
    g_dst[e] = dst;
    atomicAdd(&g_cnt[dst], 1.f);
}
__global__ void k_embed(const float* __restrict__ x, const float* __restrict__ pos,
                        const float* __restrict__ W_es, const float* __restrict__ b_es,
                        const float* __restrict__ W_ev) {
    int idx = blockIdx.x*blockDim.x + threadIdx.x;
    if (idx >= Nn*Ff) return;
    int n = idx >> 5, f = idx & 31;
    const float* xr = x + n*5;
    float s = b_es[f], ev = 0.f;
    #pragma unroll
    for (int k = 0; k < 5; k++) {
        float xv = xr[k];
        s  += xv * W_es[k*Ff + f];
        ev += xv * W_ev[k*Ff + f];
    }
    g_s[idx] = s;
    float p0 = pos[n*3+0], p1 = pos[n*3+1], p2 = pos[n*3+2];
    g_v0[idx] = ev*p0;
    g_v1[idx] = ev*p1;
    g_v2[idx] = ev*p2;
}

// ---------------- HMMA fused message kernel (R7 champion, verbatim) ----------------
// Tile = 128 edges, 256 threads (8 warps). Warp w owns edges [w*16, w*16+16).
// A (hidden acts, bf16 hi/lo) [128][72 pad], B (W2^T, bf16 hi/lo) [96][72 pad].
// 3-pass split mma: Ah*Bh + Ah*Bl + Al*Bh, fp32 acc (bias pre-loaded).
#define OFF_BH  0
#define OFF_BL  13824
#define OFF_AH  27648
#define OFF_AL  46080
#define OFF_W1S 64512
#define OFF_B1S 65792
#define OFF_B2S 66048
#define OFF_US  66432
#define OFF_SRC 67968
#define OFF_DST 68480
#define TC_SMEM 68992
__global__ void __launch_bounds__(256, 2)
k_msg_mma(const float* __restrict__ W1, const float* __restrict__ b1,
          const float* __restrict__ W2, const float* __restrict__ b2) {
    extern __shared__ char smc[];
    uint16_t* BH = (uint16_t*)(smc + OFF_BH);
    uint16_t* BL = (uint16_t*)(smc + OFF_BL);
    float* w1s = (float*)(smc + OFF_W1S);
    float* b1s = (float*)(smc + OFF_B1S);
    float* b2s = (float*)(smc + OFF_B2S);
    float* us  = (float*)(smc + OFF_US);
    int* srcs  = (int*)(smc + OFF_SRC);
    int* dsts  = (int*)(smc + OFF_DST);
    const uint32_t* AH32 = (const uint32_t*)(smc + OFF_AH);
    const uint32_t* AL32 = (const uint32_t*)(smc + OFF_AL);
    const uint32_t* BH32 = (const uint32_t*)(smc + OFF_BH);
    const uint32_t* BL32 = (const uint32_t*)(smc + OFF_BL);

    int tid = threadIdx.x;
    // stage weights once per block
    for (int i = tid; i < 320; i += 256) w1s[i] = W1[i];
    for (int i = tid; i < 64;  i += 256) b1s[i] = b1[i];
    for (int i = tid; i < 96;  i += 256) b2s[i] = b2[i];
    for (int idx = tid; idx < 96*64; idx += 256) {
        int n = idx >> 6, k = idx & 63;
        uint16_t h, l; bf16split(W2[k*96 + n], h, l);
        BH[n*72 + k] = h;
        BL[n*72 + k] = l;
    }

    int lane = tid & 31, warp = tid >> 5;
    int m0 = warp * 16;
    int r = lane >> 2, q = lane & 3;

    for (int tile = blockIdx.x; tile < NT; tile += gridDim.x) {
        __syncthreads();   // prior tile's smem reads done (and weight staging on 1st iter)
        int e0 = tile * 128;

        // --- MLP1 + bf16 split into A smem; stage edge meta ---
        {
            int e = tid >> 1;
            int jh = (tid & 1) * 32;
            const float* ein = &g_edge_in[(e0 + e)*5];
            float x0 = ein[0], x1 = ein[1], x2 = ein[2], x3 = ein[3], x4 = ein[4];
            uint32_t* AHw = (uint32_t*)(smc + OFF_AH) + e*36 + (jh >> 1);
            uint32_t* ALw = (uint32_t*)(smc + OFF_AL) + e*36 + (jh >> 1);
            #pragma unroll
            for (int i = 0; i < 16; i++) {
                int j = jh + 2*i;
                float2 bb = *(const float2*)&b1s[j];
                float a0 = bb.x, a1 = bb.y;
                float2 w;
                w = *(const float2*)&w1s[0*64 + j]; a0 = fmaf(x0, w.x, a0); a1 = fmaf(x0, w.y, a1);
                w = *(const float2*)&w1s[1*64 + j]; a0 = fmaf(x1, w.x, a0); a1 = fmaf(x1, w.y, a1);
                w = *(const float2*)&w1s[2*64 + j]; a0 = fmaf(x2, w.x, a0); a1 = fmaf(x2, w.y, a1);
                w = *(const float2*)&w1s[3*64 + j]; a0 = fmaf(x3, w.x, a0); a1 = fmaf(x3, w.y, a1);
                w = *(const float2*)&w1s[4*64 + j]; a0 = fmaf(x4, w.x, a0); a1 = fmaf(x4, w.y, a1);
                a0 = elu_fast(a0); a1 = elu_fast(a1);
                uint16_t h0,l0,h1,l1;
                bf16split(a0, h0, l0); bf16split(a1, h1, l1);
                AHw[i] = ((uint32_t)h1 << 16) | h0;
                ALw[i] = ((uint32_t)l1 << 16) | l0;
            }
            if (tid < 128) { srcs[tid] = g_src[e0 + tid]; dsts[tid] = g_dst[e0 + tid]; }
            for (int i = tid; i < 384; i += 256) us[i] = g_u[e0*3 + i];
        }
        __syncthreads();

        // --- GEMM2 via 3-pass split HMMA, bias preloaded ---
        float acc[12][4];
        #pragma unroll
        for (int nt = 0; nt < 12; nt++) {
            float2 bb = *(const float2*)&b2s[nt*8 + q*2];
            acc[nt][0] = bb.x; acc[nt][1] = bb.y;
            acc[nt][2] = bb.x; acc[nt][3] = bb.y;
        }
        #pragma unroll
        for (int ks = 0; ks < 4; ks++) {
            int k2 = ks*8 + q;
            int ra = (m0 + r)*36 + k2;
            int rb = (m0 + r + 8)*36 + k2;
            uint32_t ah[4], al[4];
            ah[0] = AH32[ra]; ah[1] = AH32[rb]; ah[2] = AH32[ra+4]; ah[3] = AH32[rb+4];
            al[0] = AL32[ra]; al[1] = AL32[rb]; al[2] = AL32[ra+4]; al[3] = AL32[rb+4];
            #pragma unroll
            for (int nt = 0; nt < 12; nt++) {
                int bi = (nt*8 + r)*36 + k2;
                uint32_t bh[2] = { BH32[bi], BH32[bi+4] };
                uint32_t bl[2] = { BL32[bi], BL32[bi+4] };
                mma16816(acc[nt], ah, bh);
                mma16816(acc[nt], ah, bl);
                mma16816(acc[nt], al, bh);
            }
        }

        // --- epilogue: messages + RED.128 scatter from fragments ---
        #pragma unroll
        for (int half = 0; half < 2; half++) {
            int e = m0 + r + half*8;
            int src = srcs[e], dst = dsts[e];
            float u0 = us[e*3+0], u1 = us[e*3+1], u2 = us[e*3+2];
            const float* srow = g_s + src*Ff;
            const float* p0r = g_v0 + src*Ff;
            const float* p1r = g_v1 + src*Ff;
            const float* p2r = g_v2 + src*Ff;
            float4* arow = g_acc + dst*Ff;
            #pragma unroll
            for (int nt = 0; nt < 4; nt++) {
                int f = nt*8 + q*2;
                float gs0 = acc[nt  ][half*2+0], gs1 = acc[nt  ][half*2+1];
                float gv0 = acc[nt+4][half*2+0], gv1 = acc[nt+4][half*2+1];
                float gt0 = acc[nt+8][half*2+0], gt1 = acc[nt+8][half*2+1];
                float2 ss = *(const float2*)&srow[f];
                float2 p0 = *(const float2*)&p0r[f];
                float2 p1 = *(const float2*)&p1r[f];
                float2 p2 = *(const float2*)&p2r[f];
                float t0 = gt0*ss.x, t1 = gt1*ss.y;
                atomicAdd(&arow[f],
                    make_float4(gs0*ss.x, fmaf(gv0, p0.x, t0*u0),
                                fmaf(gv0, p1.x, t0*u1), fmaf(gv0, p2.x, t0*u2)));
                atomicAdd(&arow[f+1],
                    make_float4(gs1*ss.y, fmaf(gv1, p0.y, t1*u0),
                                fmaf(gv1, p1.y, t1*u1), fmaf(gv1, p2.y, t1*u2)));
            }
        }
    }
}

// ---------------- per-layer node update: residual s,v (+ optional acc reset; invden folded) ----
__global__ void k_update(const float* __restrict__ Ws, const float* __restrict__ Wv, int reset) {
    __shared__ float  wss[1024], wvs[1024];
    __shared__ float4 msh[4][32];
    int tid = threadIdx.x;
    for (int i = tid; i < 1024; i += 128) { wss[i] = Ws[i]; wvs[i] = Wv[i]; }
    __syncthreads();
    int w = tid >> 5, lane = tid & 31;
    int node = blockIdx.x*4 + w;
    if (node >= Nn) return;
    float invd = 1.f / fmaxf(g_cnt[node], 1.f);
    float4 a = g_acc[node*Ff + lane];
    if (reset) g_acc[node*Ff + lane] = make_float4(0.f,0.f,0.f,0.f);
    msh[w][lane] = make_float4(a.x*invd, a.y*invd, a.z*invd, a.w*invd);
    __syncwarp();
    float so = 0.f, v0 = 0.f, v1 = 0.f, v2 = 0.f;
    #pragma unroll
    for (int f = 0; f < 32; f++) {
        float4 m = msh[w][f];
        float wsv = wss[f*32 + lane];
        float wvv = wvs[f*32 + lane];
        so += m.x*wsv;
        v0 += m.y*wvv; v1 += m.z*wvv; v2 += m.w*wvv;
    }
    int i = node*Ff + lane;
    g_s[i] += elu1(so);
    g_v0[i] += v0; g_v1[i] += v1; g_v2[i] += v2;
}

// ---------------- invariant map + graph pooling (atomic; gcnt folded) ----------------
__global__ void k_inv(const float* __restrict__ W_inv, const float* __restrict__ b_inv,
                      const int* __restrict__ batch) {
    __shared__ float wi[64*128];
    __shared__ float bi[128];
    __shared__ float feat[4][64];
    int tid = threadIdx.x;
    for (int i = tid; i < 64*128; i += 128) wi[i] = W_inv[i];
    if (tid < 128) bi[tid] = b_inv[tid];
    __syncthreads();
    int w = tid >> 5, lane = tid & 31;
    int nwarps = gridDim.x*4;
    for (int node = blockIdx.x*4 + w; node < Nn; node += nwarps) {
        int i = node*Ff + lane;
        float sval = g_s[i];
        float a0 = g_v0[i], a1 = g_v1[i], a2 = g_v2[i];
        float vn = sqrtf(a0*a0 + a1*a1 + a2*a2 + EPSf);
        feat[w][lane]      = sval;
        feat[w][32 + lane] = vn;
        __syncwarp();
        int b = batch[node];
        if (lane == 0) atomicAdd(&g_gcnt[b], 1.f);
        #pragma unroll
        for (int rr = 0; rr < 4; rr++) {
            int c = lane + 32*rr;
            float acc = bi[c];
            #pragma unroll 8
            for (int k = 0; k < 64; k++) acc += feat[w][k] * wi[k*128 + c];
            atomicAdd(&g_xg[b*NINVc + c], acc);
        }
        __syncwarp();
    }
}

// ---------------- head ----------------
__global__ void k_pool_bn1() {
    __shared__ float ssum[256], ssq[256];
    int c = blockIdx.x, tid = threadIdx.x;
    float s = 0.f, q = 0.f;
    for (int g = tid; g < Gc; g += 256) {
        float val = g_xg[g*NINVc + c] / fmaxf(g_gcnt[g], 1.f);
        g_xgp[g*NINVc + c] = val;
        s += val; q += val*val;
    }
    ssum[tid] = s; ssq[tid] = q; __syncthreads();
    for (int st = 128; st > 0; st >>= 1) {
        if (tid < st) { ssum[tid] += ssum[tid+st]; ssq[tid] += ssq[tid+st]; }
        __syncthreads();
    }
    if (tid == 0) {
        float m = ssum[0] / (float)Gc;
        float var = ssq[0] / (float)Gc - m*m;
        g_mean1[c] = m;
        g_rstd1[c] = rsqrtf(var + 1e-5f);
    }
}
__global__ void k_fc1(const float* __restrict__ g1, const float* __restrict__ be1,
                      const float* __restrict__ Wf1, const float* __restrict__ bf1) {
    __shared__ float a[128];
    int g = blockIdx.x, j = threadIdx.x;
    float xv = g_xgp[g*NINVc + j];
    a[j] = elu1((xv - g_mean1[j]) * g_rstd1[j] * g1[j] + be1[j]);
    __syncthreads();
    float acc = bf1[j];
    #pragma unroll 8
    for (int k = 0; k < 128; k++) acc += a[k] * Wf1[k*128 + j];
    g_z1[g*NINVc + j] = acc;
}
__global__ void k_bn2() {
    __shared__ float ssum[256], ssq[256];
    int c = blockIdx.x, tid = threadIdx.x;
    float s = 0.f, q = 0.f;
    for (int g = tid; g < Gc; g += 256) {
        float val = g_z1[g*NINVc + c];
        s += val; q += val*val;
    }
    ssum[tid] = s; ssq[tid] = q; __syncthreads();
    for (int st = 128; st > 0; st >>= 1) {
        if (tid < st) { ssum[tid] += ssum[tid+st]; ssq[tid] += ssq[tid+st]; }
        __syncthreads();
    }
    if (tid == 0) {
        float m = ssum[0] / (float)Gc;
        float var = ssq[0] / (float)Gc - m*m;
        g_mean2[c] = m;
        g_rstd2[c] = rsqrtf(var + 1e-5f);
    }
}
__global__ void k_head(const float* __restrict__ g2, const float* __restrict__ be2,
                       const float* __restrict__ Wf2, const float* __restrict__ bf2,
                       float* __restrict__ out) {
    int w = threadIdx.x >> 5, lane = threadIdx.x & 31;
    int g = blockIdx.x*4 + w;
    if (g >= Gc) return;
    float p = 0.f;
    for (int k = lane; k < 128; k += 32) {
        float zv = g_z1[g*NINVc + k];
        float av = elu1((zv - g_mean2[k]) * g_rstd2[k] * g2[k] + be2[k]);
        p += av * Wf2[k];
    }
    #pragma unroll
    for (int off = 16; off; off >>= 1) p += __shfl_down_sync(0xffffffffu, p, off);
    if (lane == 0) out[g] = p + bf2[0];
}

// ---------------- launch ----------------
extern "C" void kernel_launch(void* const* d_in, const int* in_sizes, int n_in,
                              void* d_out, int out_size) {
    const float* x     = (const float*)d_in[0];
    const float* pos   = (const float*)d_in[1];
    const int*   ei    = (const int*)d_in[2];     // int32 (JAX x64 disabled)
    const float* eattr = (const float*)d_in[3];
    const int*   batch = (const int*)d_in[4];     // int32
    const float* W_es  = (const float*)d_in[5];
    const float* b_es  = (const float*)d_in[6];
    const float* W_ev  = (const float*)d_in[7];
    const float* W1    = (const float*)d_in[8];
    const float* b1    = (const float*)d_in[9];
    const float* W2    = (const float*)d_in[10];
    const float* b2    = (const float*)d_in[11];
    const float* Ws    = (const float*)d_in[12];
    const float* Wv    = (const float*)d_in[13];
    const float* W_inv = (const float*)d_in[14];
    const float* b_inv = (const float*)d_in[15];
    const float* g1    = (const float*)d_in[16];
    const float* be1   = (const float*)d_in[17];
    const float* Wf1   = (const float*)d_in[18];
    const float* bf1   = (const float*)d_in[19];
    const float* g2    = (const float*)d_in[20];
    const float* be2   = (const float*)d_in[21];
    const float* Wf2   = (const float*)d_in[22];
    const float* bf2   = (const float*)d_in[23];
    float* out = (float*)d_out;

    cudaFuncSetAttribute(k_msg_mma, cudaFuncAttributeMaxDynamicSharedMemorySize, TC_SMEM);

    int ztotal = Nn*Ff + Nn + Gc + Gc*NINVc;
    k_zero_all<<<(ztotal + 255)/256, 256>>>();                       // #1
    k_edge_prep<<<(Ee + 255)/256, 256>>>(pos, ei, eattr);            // #2
    k_embed<<<(Nn*Ff + 255)/256, 256>>>(x, pos, W_es, b_es, W_ev);   // #3

    // layer 0 k_msg_mma is launch #4 -> ncu -s 5 -c 1 captures it
    k_msg_mma<<<444, 256, TC_SMEM>>>(W1, b1, W2, b2);                // #4
    k_update<<<Nn/4, 128>>>(Ws, Wv, 1);                              // #5

    for (int l = 1; l < NLc; l++) {
        k_msg_mma<<<444, 256, TC_SMEM>>>(W1 + l*5*Hc, b1 + l*Hc,
                                         W2 + l*Hc*3*Ff, b2 + l*3*Ff);
        k_update<<<Nn/4, 128>>>(Ws + l*Ff*Ff, Wv + l*Ff*Ff, (l < NLc-1) ? 1 : 0);
    }

    k_inv<<<1024, 128>>>(W_inv, b_inv, batch);
    k_pool_bn1<<<NINVc, 256>>>();
    k_fc1<<<Gc, 128>>>(g1, be1, Wf1, bf1);
    k_bn2<<<NINVc, 256>>>();
    k_head<<<Gc/4, 128>>>(g2, be2, Wf2, bf2, out);
}

// round 14
// speedup vs baseline: 1.2748x; 1.0468x over previous
#include <cuda_runtime.h>
#include <cuda_bf16.h>
#include <math.h>
#include <cstdint>

#define Nn   50000
#define Ee   800000
#define Ff   32
#define NINVc 128
#define NLc  4
#define Hc   64
#define Gc   2048
#define EPSf 1e-6f
#define NT   (Ee/128)   // 6250 tiles of 128 edges

// ---------------- device scratch (no allocs allowed) ----------------
__device__ __align__(16) float  g_edge_in[Ee*5];   // dst-sorted
__device__ float  g_u[Ee*3];                       // dst-sorted
__device__ int    g_src[Ee];                       // dst-sorted
__device__ int    g_dst[Ee];                       // dst-sorted
__device__ float4 g_sv[Nn*Ff];        // {s, v0, v1, v2} interleaved node state
__device__ float4 g_acc[Nn*Ff];       // {ms, mv0, mv1, mv2}
__device__ int    g_deg[Nn];
__device__ int    g_woff[Nn];
__device__ float  g_xg[Gc*NINVc];
__device__ float  g_gcnt[Gc];
__device__ float  g_xgp[Gc*NINVc];
__device__ float  g_z1[Gc*NINVc];
__device__ float  g_mean1[NINVc], g_rstd1[NINVc], g_mean2[NINVc], g_rstd2[NINVc];

__device__ __forceinline__ float elu1(float x) { return x > 0.f ? x : expm1f(x); }
__device__ __forceinline__ float elu_fast(float x) { return x > 0.f ? x : (__expf(x) - 1.f); }

// warp-level bf16 mma (sm_80+ baseline PTX; works on plain sm_103 target)
__device__ __forceinline__ void mma16816(float* d, const uint32_t* a, const uint32_t* b) {
    asm volatile(
        "mma.sync.aligned.m16n8k16.row.col.f32.bf16.bf16.f32 "
        "{%0,%1,%2,%3}, {%4,%5,%6,%7}, {%8,%9}, {%0,%1,%2,%3};"
        : "+f"(d[0]), "+f"(d[1]), "+f"(d[2]), "+f"(d[3])
        : "r"(a[0]), "r"(a[1]), "r"(a[2]), "r"(a[3]), "r"(b[0]), "r"(b[1]));
}
__device__ __forceinline__ void bf16split(float x, uint16_t& h, uint16_t& l) {
    __nv_bfloat16 hb = __float2bfloat16_rn(x);
    float r = x - __bfloat162float(hb);
    __nv_bfloat16 lb = __float2bfloat16_rn(r);
    h = __bfloat16_as_ushort(hb);
    l = __bfloat16_as_ushort(lb);
}

// ---------------- #1: zero + embedding fused ----------------
__global__ void k_zero_embed(const float* __restrict__ x, const float* __restrict__ pos,
                             const float* __restrict__ W_es, const float* __restrict__ b_es,
                             const float* __restrict__ W_ev) {
    int i = blockIdx.x*blockDim.x + threadIdx.x;
    if (i < Nn*Ff) {
        g_acc[i] = make_float4(0.f,0.f,0.f,0.f);
        int n = i >> 5, f = i & 31;
        const float* xr = x + n*5;
        float s = b_es[f], ev = 0.f;
        #pragma unroll
        for (int k = 0; k < 5; k++) {
            float xv = xr[k];
            s  += xv * W_es[k*Ff + f];
            ev += xv * W_ev[k*Ff + f];
        }
        float p0 = pos[n*3+0], p1 = pos[n*3+1], p2 = pos[n*3+2];
        g_sv[i] = make_float4(s, ev*p0, ev*p1, ev*p2);
        return;
    }
    i -= Nn*Ff;
    if (i < Nn) { g_deg[i] = 0; return; }
    i -= Nn;
    if (i < Gc) { g_gcnt[i] = 0.f; return; }
    i -= Gc;
    if (i < Gc*NINVc) g_xg[i] = 0.f;
}

// ---------------- #2: dst histogram ----------------
__global__ void k_hist(const int* __restrict__ ei) {
    int e = blockIdx.x*blockDim.x + threadIdx.x;
    if (e < Ee) atomicAdd(&g_deg[ei[Ee + e]], 1);
}

// ---------------- #3: exclusive scan of degrees -> write cursors ----------------
__global__ void k_scan() {
    __shared__ int part[1024];
    int t = threadIdx.x;
    const int per = (Nn + 1023) / 1024;   // 49
    int lo = t*per, hi = min(lo + per, Nn);
    int s = 0;
    for (int i = lo; i < hi; i++) s += g_deg[i];
    part[t] = s;
    __syncthreads();
    for (int off = 1; off < 1024; off <<= 1) {
        int v = (t >= off) ? part[t - off] : 0;
        __syncthreads();
        part[t] += v;
        __syncthreads();
    }
    int run = part[t] - s;   // exclusive prefix
    for (int i = lo; i < hi; i++) { g_woff[i] = run; run += g_deg[i]; }
}

// ---------------- #4: edge prep, written to dst-sorted slots ----------------
__global__ void k_edge_prep(const float* __restrict__ pos,
                            const int* __restrict__ ei,
                            const float* __restrict__ eattr) {
    int e = blockIdx.x*blockDim.x + threadIdx.x;
    if (e >= Ee) return;
    int src = ei[e];
    int dst = ei[Ee + e];
    float dx = pos[dst*3+0] - pos[src*3+0];
    float dy = pos[dst*3+1] - pos[src*3+1];
    float dz = pos[dst*3+2] - pos[src*3+2];
    float d  = sqrtf(dx*dx + dy*dy + dz*dz + EPSf);
    float inv = 1.0f/d;
    int slot = atomicAdd(&g_woff[dst], 1);
    g_edge_in[slot*5+0] = d;
    g_edge_in[slot*5+1] = eattr[e*4+0];
    g_edge_in[slot*5+2] = eattr[e*4+1];
    g_edge_in[slot*5+3] = eattr[e*4+2];
    g_edge_in[slot*5+4] = eattr[e*4+3];
    g_u[slot*3+0] = dx*inv;
    g_u[slot*3+1] = dy*inv;
    g_u[slot*3+2] = dz*inv;
    g_src[slot] = src;
    g_dst[slot] = dst;
}

// ---------------- HMMA fused message kernel (R7 mainloop; interleaved + merged epilogue) ----
#define OFF_BH  0
#define OFF_BL  13824
#define OFF_AH  27648
#define OFF_AL  46080
#define OFF_W1S 64512
#define OFF_B1S 65792
#define OFF_B2S 66048
#define OFF_US  66432
#define OFF_SRC 67968
#define OFF_DST 68480
#define TC_SMEM 68992
__global__ void __launch_bounds__(256, 2)
k_msg_mma(const float* __restrict__ W1, const float* __restrict__ b1,
          const float* __restrict__ W2, const float* __restrict__ b2) {
    extern __shared__ char smc[];
    uint16_t* BH = (uint16_t*)(smc + OFF_BH);
    uint16_t* BL = (uint16_t*)(smc + OFF_BL);
    float* w1s = (float*)(smc + OFF_W1S);
    float* b1s = (float*)(smc + OFF_B1S);
    float* b2s = (float*)(smc + OFF_B2S);
    float* us  = (float*)(smc + OFF_US);
    int* srcs  = (int*)(smc + OFF_SRC);
    int* dsts  = (int*)(smc + OFF_DST);
    const uint32_t* AH32 = (const uint32_t*)(smc + OFF_AH);
    const uint32_t* AL32 = (const uint32_t*)(smc + OFF_AL);
    const uint32_t* BH32 = (const uint32_t*)(smc + OFF_BH);
    const uint32_t* BL32 = (const uint32_t*)(smc + OFF_BL);

    int tid = threadIdx.x;
    for (int i = tid; i < 320; i += 256) w1s[i] = W1[i];
    for (int i = tid; i < 64;  i += 256) b1s[i] = b1[i];
    for (int i = tid; i < 96;  i += 256) b2s[i] = b2[i];
    for (int idx = tid; idx < 96*64; idx += 256) {
        int n = idx >> 6, k = idx & 63;
        uint16_t h, l; bf16split(W2[k*96 + n], h, l);
        BH[n*72 + k] = h;
        BL[n*72 + k] = l;
    }

    int lane = tid & 31, warp = tid >> 5;
    int m0 = warp * 16;
    int r = lane >> 2, q = lane & 3;

    for (int tile = blockIdx.x; tile < NT; tile += gridDim.x) {
        __syncthreads();
        int e0 = tile * 128;

        // --- MLP1 + bf16 split into A smem; stage edge meta ---
        {
            int e = tid >> 1;
            int jh = (tid & 1) * 32;
            const float* ein = &g_edge_in[(e0 + e)*5];
            float x0 = ein[0], x1 = ein[1], x2 = ein[2], x3 = ein[3], x4 = ein[4];
            uint32_t* AHw = (uint32_t*)(smc + OFF_AH) + e*36 + (jh >> 1);
            uint32_t* ALw = (uint32_t*)(smc + OFF_AL) + e*36 + (jh >> 1);
            #pragma unroll
            for (int i = 0; i < 16; i++) {
                int j = jh + 2*i;
                float2 bb = *(const float2*)&b1s[j];
                float a0 = bb.x, a1 = bb.y;
                float2 w;
                w = *(const float2*)&w1s[0*64 + j]; a0 = fmaf(x0, w.x, a0); a1 = fmaf(x0, w.y, a1);
                w = *(const float2*)&w1s[1*64 + j]; a0 = fmaf(x1, w.x, a0); a1 = fmaf(x1, w.y, a1);
                w = *(const float2*)&w1s[2*64 + j]; a0 = fmaf(x2, w.x, a0); a1 = fmaf(x2, w.y, a1);
                w = *(const float2*)&w1s[3*64 + j]; a0 = fmaf(x3, w.x, a0); a1 = fmaf(x3, w.y, a1);
                w = *(const float2*)&w1s[4*64 + j]; a0 = fmaf(x4, w.x, a0); a1 = fmaf(x4, w.y, a1);
                a0 = elu_fast(a0); a1 = elu_fast(a1);
                uint16_t h0,l0,h1,l1;
                bf16split(a0, h0, l0); bf16split(a1, h1, l1);
                AHw[i] = ((uint32_t)h1 << 16) | h0;
                ALw[i] = ((uint32_t)l1 << 16) | l0;
            }
            if (tid < 128) { srcs[tid] = g_src[e0 + tid]; dsts[tid] = g_dst[e0 + tid]; }
            for (int i = tid; i < 384; i += 256) us[i] = g_u[e0*3 + i];
        }
        __syncthreads();

        // --- GEMM2 via 3-pass split HMMA, bias preloaded ---
        float acc[12][4];
        #pragma unroll
        for (int nt = 0; nt < 12; nt++) {
            float2 bb = *(const float2*)&b2s[nt*8 + q*2];
            acc[nt][0] = bb.x; acc[nt][1] = bb.y;
            acc[nt][2] = bb.x; acc[nt][3] = bb.y;
        }
        #pragma unroll
        for (int ks = 0; ks < 4; ks++) {
            int k2 = ks*8 + q;
            int ra = (m0 + r)*36 + k2;
            int rb = (m0 + r + 8)*36 + k2;
            uint32_t ah[4], al[4];
            ah[0] = AH32[ra]; ah[1] = AH32[rb]; ah[2] = AH32[ra+4]; ah[3] = AH32[rb+4];
            al[0] = AL32[ra]; al[1] = AL32[rb]; al[2] = AL32[ra+4]; al[3] = AL32[rb+4];
            #pragma unroll
            for (int nt = 0; nt < 12; nt++) {
                int bi = (nt*8 + r)*36 + k2;
                uint32_t bh[2] = { BH32[bi], BH32[bi+4] };
                uint32_t bl[2] = { BL32[bi], BL32[bi+4] };
                mma16816(acc[nt], ah, bh);
                mma16816(acc[nt], ah, bl);
                mma16816(acc[nt], al, bh);
            }
        }

        // --- epilogue: interleaved float4 gathers + half-merged RED.128 scatter ---
        {
            int eL = m0 + r, eH = eL + 8;
            int srcL = srcs[eL], srcH = srcs[eH];
            int dstL = dsts[eL], dstH = dsts[eH];
            float uL0 = us[eL*3+0], uL1 = us[eL*3+1], uL2 = us[eL*3+2];
            float uH0 = us[eH*3+0], uH1 = us[eH*3+1], uH2 = us[eH*3+2];
            const float4* svL = g_sv + srcL*Ff;
            const float4* svH = g_sv + srcH*Ff;
            float4* aL = g_acc + dstL*Ff;
            float4* aH = g_acc + dstH*Ff;
            bool merge = (dstL == dstH);
            #pragma unroll
            for (int nt = 0; nt < 4; nt++) {
                int f0 = nt*8 + q*2;
                float4 nL0 = svL[f0], nL1 = svL[f0+1];
                float4 nH0 = svH[f0], nH1 = svH[f0+1];
                float gsL0 = acc[nt  ][0], gsL1 = acc[nt  ][1];
                float gsH0 = acc[nt  ][2], gsH1 = acc[nt  ][3];
                float gvL0 = acc[nt+4][0], gvL1 = acc[nt+4][1];
                float gvH0 = acc[nt+4][2], gvH1 = acc[nt+4][3];
                float gtL0 = acc[nt+8][0], gtL1 = acc[nt+8][1];
                float gtH0 = acc[nt+8][2], gtH1 = acc[nt+8][3];
                float tL0 = gtL0*nL0.x, tL1 = gtL1*nL1.x;
                float tH0 = gtH0*nH0.x, tH1 = gtH1*nH1.x;
                float4 mL0 = make_float4(gsL0*nL0.x, fmaf(gvL0, nL0.y, tL0*uL0),
                                         fmaf(gvL0, nL0.z, tL0*uL1), fmaf(gvL0, nL0.w, tL0*uL2));
                float4 mL1 = make_float4(gsL1*nL1.x, fmaf(gvL1, nL1.y, tL1*uL0),
                                         fmaf(gvL1, nL1.z, tL1*uL1), fmaf(gvL1, nL1.w, tL1*uL2));
                float4 mH0 = make_float4(gsH0*nH0.x, fmaf(gvH0, nH0.y, tH0*uH0),
                                         fmaf(gvH0, nH0.z, tH0*uH1), fmaf(gvH0, nH0.w, tH0*uH2));
                float4 mH1 = make_float4(gsH1*nH1.x, fmaf(gvH1, nH1.y, tH1*uH0),
                                         fmaf(gvH1, nH1.z, tH1*uH1), fmaf(gvH1, nH1.w, tH1*uH2));
                if (merge) {
                    atomicAdd(&aL[f0],   make_float4(mL0.x+mH0.x, mL0.y+mH0.y, mL0.z+mH0.z, mL0.w+mH0.w));
                    atomicAdd(&aL[f0+1], make_float4(mL1.x+mH1.x, mL1.y+mH1.y, mL1.z+mH1.z, mL1.w+mH1.w));
                } else {
                    atomicAdd(&aL[f0],   mL0);
                    atomicAdd(&aL[f0+1], mL1);
                    atomicAdd(&aH[f0],   mH0);
                    atomicAdd(&aH[f0+1], mH1);
                }
            }
        }
    }
}

// ---------------- per-layer node update: residual s,v (+ optional acc reset) ----------------
__global__ void k_update(const float* __restrict__ Ws, const float* __restrict__ Wv, int reset) {
    __shared__ float  wss[1024], wvs[1024];
    __shared__ float4 msh[4][32];
    int tid = threadIdx.x;
    for (int i = tid; i < 1024; i += 128) { wss[i] = Ws[i]; wvs[i] = Wv[i]; }
    __syncthreads();
    int w = tid >> 5, lane = tid & 31;
    int node = blockIdx.x*4 + w;
    if (node >= Nn) return;
    float invd = 1.f / fmaxf((float)g_deg[node], 1.f);
    float4 a = g_acc[node*Ff + lane];
    if (reset) g_acc[node*Ff + lane] = make_float4(0.f,0.f,0.f,0.f);
    msh[w][lane] = make_float4(a.x*invd, a.y*invd, a.z*invd, a.w*invd);
    __syncwarp();
    float so = 0.f, v0 = 0.f, v1 = 0.f, v2 = 0.f;
    #pragma unroll
    for (int f = 0; f < 32; f++) {
        float4 m = msh[w][f];
        float wsv = wss[f*32 + lane];
        float wvv = wvs[f*32 + lane];
        so += m.x*wsv;
        v0 += m.y*wvv; v1 += m.z*wvv; v2 += m.w*wvv;
    }
    int i = node*Ff + lane;
    float4 sv = g_sv[i];
    sv.x += elu1(so);
    sv.y += v0; sv.z += v1; sv.w += v2;
    g_sv[i] = sv;
}

// ---------------- invariant map + graph pooling (atomic; gcnt folded) ----------------
__global__ void k_inv(const float* __restrict__ W_inv, const float* __restrict__ b_inv,
                      const int* __restrict__ batch) {
    __shared__ float wi[64*128];
    __shared__ float bi[128];
    __shared__ float feat[4][64];
    int tid = threadIdx.x;
    for (int i = tid; i < 64*128; i += 128) wi[i] = W_inv[i];
    if (tid < 128) bi[tid] = b_inv[tid];
    __syncthreads();
    int w = tid >> 5, lane = tid & 31;
    int nwarps = gridDim.x*4;
    for (int node = blockIdx.x*4 + w; node < Nn; node += nwarps) {
        float4 sv = g_sv[node*Ff + lane];
        float vn = sqrtf(sv.y*sv.y + sv.z*sv.z + sv.w*sv.w + EPSf);
        feat[w][lane]      = sv.x;
        feat[w][32 + lane] = vn;
        __syncwarp();
        int b = batch[node];
        if (lane == 0) atomicAdd(&g_gcnt[b], 1.f);
        #pragma unroll
        for (int rr = 0; rr < 4; rr++) {
            int c = lane + 32*rr;
            float acc = bi[c];
            #pragma unroll 8
            for (int k = 0; k < 64; k++) acc += feat[w][k] * wi[k*128 + c];
            atomicAdd(&g_xg[b*NINVc + c], acc);
        }
        __syncwarp();
    }
}

// ---------------- head ----------------
__global__ void k_pool_bn1() {
    __shared__ float ssum[256], ssq[256];
    int c = blockIdx.x, tid = threadIdx.x;
    float s = 0.f, q = 0.f;
    for (int g = tid; g < Gc; g += 256) {
        float val = g_xg[g*NINVc + c] / fmaxf(g_gcnt[g], 1.f);
        g_xgp[g*NINVc + c] = val;
        s += val; q += val*val;
    }
    ssum[tid] = s; ssq[tid] = q; __syncthreads();
    for (int st = 128; st > 0; st >>= 1) {
        if (tid < st) { ssum[tid] += ssum[tid+st]; ssq[tid] += ssq[tid+st]; }
        __syncthreads();
    }
    if (tid == 0) {
        float m = ssum[0] / (float)Gc;
        float var = ssq[0] / (float)Gc - m*m;
        g_mean1[c] = m;
        g_rstd1[c] = rsqrtf(var + 1e-5f);
    }
}
__global__ void k_fc1(const float* __restrict__ g1, const float* __restrict__ be1,
                      const float* __restrict__ Wf1, const float* __restrict__ bf1) {
    __shared__ float a[128];
    int g = blockIdx.x, j = threadIdx.x;
    float xv = g_xgp[g*NINVc + j];
    a[j] = elu1((xv - g_mean1[j]) * g_rstd1[j] * g1[j] + be1[j]);
    __syncthreads();
    float acc = bf1[j];
    #pragma unroll 8
    for (int k = 0; k < 128; k++) acc += a[k] * Wf1[k*128 + j];
    g_z1[g*NINVc + j] = acc;
}
__global__ void k_bn2() {
    __shared__ float ssum[256], ssq[256];
    int c = blockIdx.x, tid = threadIdx.x;
    float s = 0.f, q = 0.f;
    for (int g = tid; g < Gc; g += 256) {
        float val = g_z1[g*NINVc + c];
        s += val; q += val*val;
    }
    ssum[tid] = s; ssq[tid] = q; __syncthreads();
    for (int st = 128; st > 0; st >>= 1) {
        if (tid < st) { ssum[tid] += ssum[tid+st]; ssq[tid] += ssq[tid+st]; }
        __syncthreads();
    }
    if (tid == 0) {
        float m = ssum[0] / (float)Gc;
        float var = ssq[0] / (float)Gc - m*m;
        g_mean2[c] = m;
        g_rstd2[c] = rsqrtf(var + 1e-5f);
    }
}
__global__ void k_head(const float* __restrict__ g2, const float* __restrict__ be2,
                       const float* __restrict__ Wf2, const float* __restrict__ bf2,
                       float* __restrict__ out) {
    int w = threadIdx.x >> 5, lane = threadIdx.x & 31;
    int g = blockIdx.x*4 + w;
    if (g >= Gc) return;
    float p = 0.f;
    for (int k = lane; k < 128; k += 32) {
        float zv = g_z1[g*NINVc + k];
        float av = elu1((zv - g_mean2[k]) * g_rstd2[k] * g2[k] + be2[k]);
        p += av * Wf2[k];
    }
    #pragma unroll
    for (int off = 16; off; off >>= 1) p += __shfl_down_sync(0xffffffffu, p, off);
    if (lane == 0) out[g] = p + bf2[0];
}

// ---------------- launch ----------------
extern "C" void kernel_launch(void* const* d_in, const int* in_sizes, int n_in,
                              void* d_out, int out_size) {
    const float* x     = (const float*)d_in[0];
    const float* pos   = (const float*)d_in[1];
    const int*   ei    = (const int*)d_in[2];     // int32 (JAX x64 disabled)
    const float* eattr = (const float*)d_in[3];
    const int*   batch = (const int*)d_in[4];     // int32
    const float* W_es  = (const float*)d_in[5];
    const float* b_es  = (const float*)d_in[6];
    const float* W_ev  = (const float*)d_in[7];
    const float* W1    = (const float*)d_in[8];
    const float* b1    = (const float*)d_in[9];
    const float* W2    = (const float*)d_in[10];
    const float* b2    = (const float*)d_in[11];
    const float* Ws    = (const float*)d_in[12];
    const float* Wv    = (const float*)d_in[13];
    const float* W_inv = (const float*)d_in[14];
    const float* b_inv = (const float*)d_in[15];
    const float* g1    = (const float*)d_in[16];
    const float* be1   = (const float*)d_in[17];
    const float* Wf1   = (const float*)d_in[18];
    const float* bf1   = (const float*)d_in[19];
    const float* g2    = (const float*)d_in[20];
    const float* be2   = (const float*)d_in[21];
    const float* Wf2   = (const float*)d_in[22];
    const float* bf2   = (const float*)d_in[23];
    float* out = (float*)d_out;

    cudaFuncSetAttribute(k_msg_mma, cudaFuncAttributeMaxDynamicSharedMemorySize, TC_SMEM);

    int ztotal = Nn*Ff + Nn + Gc + Gc*NINVc;
    k_zero_embed<<<(ztotal + 255)/256, 256>>>(x, pos, W_es, b_es, W_ev);   // #1
    k_hist<<<(Ee + 255)/256, 256>>>(ei);                                   // #2
    k_scan<<<1, 1024>>>();                                                 // #3
    k_edge_prep<<<(Ee + 255)/256, 256>>>(pos, ei, eattr);                  // #4

    for (int l = 0; l < NLc; l++) {
        k_msg_mma<<<444, 256, TC_SMEM>>>(W1 + l*5*Hc, b1 + l*Hc,
                                         W2 + l*Hc*3*Ff, b2 + l*3*Ff);
        k_update<<<Nn/4, 128>>>(Ws + l*Ff*Ff, Wv + l*Ff*Ff, (l < NLc-1) ? 1 : 0);
    }

    k_inv<<<1024, 128>>>(W_inv, b_inv, batch);
    k_pool_bn1<<<NINVc, 256>>>();
    k_fc1<<<Gc, 128>>>(g1, be1, Wf1, bf1);
    k_bn2<<<NINVc, 256>>>();
    k_head<<<Gc/4, 128>>>(g2, be2, Wf2, bf2, out);
}

// round 15
// speedup vs baseline: 1.3610x; 1.0676x over previous
#include <cuda_runtime.h>
#include <cuda_bf16.h>
#include <math.h>
#include <cstdint>

#define Nn   50000
#define Ee   800000
#define Ff   32
#define NINVc 128
#define NLc  4
#define Hc   64
#define Gc   2048
#define EPSf 1e-6f
#define NT   (Ee/128)   // 6250 tiles of 128 edges

// ---------------- device scratch (no allocs allowed) ----------------
__device__ __align__(16) uint32_t g_ein_pk[Ee*8];  // dst-sorted, pre-split edge inputs (hi[4],lo[4])
__device__ float  g_u[Ee*3];                       // dst-sorted
__device__ int    g_src[Ee];                       // dst-sorted
__device__ int    g_dst[Ee];                       // dst-sorted
__device__ float4 g_sv[Nn*Ff];        // {s, v0, v1, v2} interleaved node state
__device__ float4 g_acc[Nn*Ff];       // {ms, mv0, mv1, mv2}
__device__ int    g_deg[Nn];
__device__ int    g_woff[Nn];
__device__ float  g_xg[Gc*NINVc];
__device__ float  g_gcnt[Gc];
__device__ float  g_xgp[Gc*NINVc];
__device__ float  g_z1[Gc*NINVc];
__device__ float  g_mean1[NINVc], g_rstd1[NINVc], g_mean2[NINVc], g_rstd2[NINVc];

__device__ __forceinline__ float elu1(float x) { return x > 0.f ? x : expm1f(x); }
__device__ __forceinline__ float elu_fast(float x) { return x > 0.f ? x : (__expf(x) - 1.f); }

// warp-level bf16 mma (sm_80+ baseline PTX; works on plain sm_103 target)
__device__ __forceinline__ void mma16816(float* d, const uint32_t* a, const uint32_t* b) {
    asm volatile(
        "mma.sync.aligned.m16n8k16.row.col.f32.bf16.bf16.f32 "
        "{%0,%1,%2,%3}, {%4,%5,%6,%7}, {%8,%9}, {%0,%1,%2,%3};"
        : "+f"(d[0]), "+f"(d[1]), "+f"(d[2]), "+f"(d[3])
        : "r"(a[0]), "r"(a[1]), "r"(a[2]), "r"(a[3]), "r"(b[0]), "r"(b[1]));
}
__device__ __forceinline__ void mma16808(float* d, uint32_t a0, uint32_t a1, uint32_t b) {
    asm volatile(
        "mma.sync.aligned.m16n8k8.row.col.f32.bf16.bf16.f32 "
        "{%0,%1,%2,%3}, {%4,%5}, {%6}, {%0,%1,%2,%3};"
        : "+f"(d[0]), "+f"(d[1]), "+f"(d[2]), "+f"(d[3])
        : "r"(a0), "r"(a1), "r"(b));
}
__device__ __forceinline__ void bf16split(float x, uint16_t& h, uint16_t& l) {
    __nv_bfloat16 hb = __float2bfloat16_rn(x);
    float r = x - __bfloat162float(hb);
    __nv_bfloat16 lb = __float2bfloat16_rn(r);
    h = __bfloat16_as_ushort(hb);
    l = __bfloat16_as_ushort(lb);
}
// packed split of (x0, x1) -> hi u32 {bf16(x1),bf16(x0)} and lo u32 of residuals
__device__ __forceinline__ void split2(float x0, float x1, uint32_t& h, uint32_t& l) {
    uint32_t hp;
    asm("cvt.rn.satfinite.bf16x2.f32 %0, %1, %2;" : "=r"(hp) : "f"(x1), "f"(x0));
    float f0 = __uint_as_float(hp << 16);
    float f1 = __uint_as_float(hp & 0xffff0000u);
    float r0 = x0 - f0, r1 = x1 - f1;
    uint32_t lp;
    asm("cvt.rn.satfinite.bf16x2.f32 %0, %1, %2;" : "=r"(lp) : "f"(r1), "f"(r0));
    h = hp; l = lp;
}

// ---------------- #1: zero + embedding fused ----------------
__global__ void k_zero_embed(const float* __restrict__ x, const float* __restrict__ pos,
                             const float* __restrict__ W_es, const float* __restrict__ b_es,
                             const float* __restrict__ W_ev) {
    int i = blockIdx.x*blockDim.x + threadIdx.x;
    if (i < Nn*Ff) {
        g_acc[i] = make_float4(0.f,0.f,0.f,0.f);
        int n = i >> 5, f = i & 31;
        const float* xr = x + n*5;
        float s = b_es[f], ev = 0.f;
        #pragma unroll
        for (int k = 0; k < 5; k++) {
            float xv = xr[k];
            s  += xv * W_es[k*Ff + f];
            ev += xv * W_ev[k*Ff + f];
        }
        float p0 = pos[n*3+0], p1 = pos[n*3+1], p2 = pos[n*3+2];
        g_sv[i] = make_float4(s, ev*p0, ev*p1, ev*p2);
        return;
    }
    i -= Nn*Ff;
    if (i < Nn) { g_deg[i] = 0; return; }
    i -= Nn;
    if (i < Gc) { g_gcnt[i] = 0.f; return; }
    i -= Gc;
    if (i < Gc*NINVc) g_xg[i] = 0.f;
}

// ---------------- #2: dst histogram ----------------
__global__ void k_hist(const int* __restrict__ ei) {
    int e = blockIdx.x*blockDim.x + threadIdx.x;
    if (e < Ee) atomicAdd(&g_deg[ei[Ee + e]], 1);
}

// ---------------- #3: exclusive scan of degrees -> write cursors ----------------
__global__ void k_scan() {
    __shared__ int part[1024];
    int t = threadIdx.x;
    const int per = (Nn + 1023) / 1024;   // 49
    int lo = t*per, hi = min(lo + per, Nn);
    int s = 0;
    for (int i = lo; i < hi; i++) s += g_deg[i];
    part[t] = s;
    __syncthreads();
    for (int off = 1; off < 1024; off <<= 1) {
        int v = (t >= off) ? part[t - off] : 0;
        __syncthreads();
        part[t] += v;
        __syncthreads();
    }
    int run = part[t] - s;   // exclusive prefix
    for (int i = lo; i < hi; i++) { g_woff[i] = run; run += g_deg[i]; }
}

// ---------------- #4: edge prep, pre-split bf16 hi/lo, dst-sorted slots ----------------
__global__ void k_edge_prep(const float* __restrict__ pos,
                            const int* __restrict__ ei,
                            const float* __restrict__ eattr) {
    int e = blockIdx.x*blockDim.x + threadIdx.x;
    if (e >= Ee) return;
    int src = ei[e];
    int dst = ei[Ee + e];
    float dx = pos[dst*3+0] - pos[src*3+0];
    float dy = pos[dst*3+1] - pos[src*3+1];
    float dz = pos[dst*3+2] - pos[src*3+2];
    float d  = sqrtf(dx*dx + dy*dy + dz*dz + EPSf);
    float inv = 1.0f/d;
    int slot = atomicAdd(&g_woff[dst], 1);
    float ea0 = eattr[e*4+0], ea1 = eattr[e*4+1], ea2 = eattr[e*4+2], ea3 = eattr[e*4+3];
    uint32_t ph0,pl0, ph1,pl1, ph2,pl2;
    split2(d,   ea0, ph0, pl0);
    split2(ea1, ea2, ph1, pl1);
    split2(ea3, 0.f, ph2, pl2);
    ((uint4*)g_ein_pk)[slot*2]   = make_uint4(ph0, ph1, ph2, 0u);
    ((uint4*)g_ein_pk)[slot*2+1] = make_uint4(pl0, pl1, pl2, 0u);
    g_u[slot*3+0] = dx*inv;
    g_u[slot*3+1] = dy*inv;
    g_u[slot*3+2] = dz*inv;
    g_src[slot] = src;
    g_dst[slot] = dst;
}

// ---------------- HMMA fused message kernel: MLP1 (m16n8k8) -> GEMM2 (m16n8k16) in regs ----
// Tile = 128 edges, 256 threads (8 warps). Warp w owns edges [w*16, w*16+16).
// Edge-input A-frags staged pre-split from gmem; W1 B-frags resident in registers;
// MLP1 D-frags map directly onto GEMM2 A-frags (elu+split in regs, no A smem).
#define OFF_BH   0          // 13824
#define OFF_BL   13824      // 13824
#define OFF_AHK  27648      // 128*4 u32 = 2048
#define OFF_ALK  29696      // 2048
#define OFF_US   31744      // 384 f = 1536
#define OFF_SRC  33280      // 512
#define OFF_DST  33792      // 512
#define OFF_B1S  34304      // 256
#define OFF_B2S  34560      // 384
#define TC_SMEM  34944
__global__ void __launch_bounds__(256, 2)
k_msg_mma(const float* __restrict__ W1, const float* __restrict__ b1,
          const float* __restrict__ W2, const float* __restrict__ b2) {
    extern __shared__ char smc[];
    uint16_t* BH = (uint16_t*)(smc + OFF_BH);
    uint16_t* BL = (uint16_t*)(smc + OFF_BL);
    uint32_t* AHK = (uint32_t*)(smc + OFF_AHK);
    uint32_t* ALK = (uint32_t*)(smc + OFF_ALK);
    float* us  = (float*)(smc + OFF_US);
    int* srcs  = (int*)(smc + OFF_SRC);
    int* dsts  = (int*)(smc + OFF_DST);
    float* b1s = (float*)(smc + OFF_B1S);
    float* b2s = (float*)(smc + OFF_B2S);
    const uint32_t* BH32 = (const uint32_t*)(smc + OFF_BH);
    const uint32_t* BL32 = (const uint32_t*)(smc + OFF_BL);

    int tid = threadIdx.x;
    for (int i = tid; i < 64;  i += 256) b1s[i] = b1[i];
    for (int i = tid; i < 96;  i += 256) b2s[i] = b2[i];
    for (int idx = tid; idx < 96*64; idx += 256) {
        int n = idx >> 6, k = idx & 63;
        uint16_t h, l; bf16split(W2[k*96 + n], h, l);
        BH[n*72 + k] = h;
        BL[n*72 + k] = l;
    }

    int lane = tid & 31, warp = tid >> 5;
    int m0 = warp * 16;
    int r = lane >> 2, q = lane & 3;

    // W1 B-frags (m16n8k8: b = {k=2q,2q+1, n=nt*8+r}), resident in registers
    uint32_t w1h[8], w1l[8];
    {
        int k0 = 2*q, k1 = 2*q + 1;
        #pragma unroll
        for (int nt = 0; nt < 8; nt++) {
            int n = nt*8 + r;
            float x0 = (k0 < 5) ? W1[k0*64 + n] : 0.f;
            float x1 = (k1 < 5) ? W1[k1*64 + n] : 0.f;
            split2(x0, x1, w1h[nt], w1l[nt]);
        }
    }

    for (int tile = blockIdx.x; tile < NT; tile += gridDim.x) {
        __syncthreads();
        int e0 = tile * 128;
        if (tid < 128) {
            const uint4* s4 = ((const uint4*)g_ein_pk) + (e0 + tid)*2;
            *(uint4*)&AHK[tid*4] = s4[0];
            *(uint4*)&ALK[tid*4] = s4[1];
            srcs[tid] = g_src[e0 + tid];
            dsts[tid] = g_dst[e0 + tid];
        }
        for (int i = tid; i < 384; i += 256) us[i] = g_u[e0*3 + i];
        __syncthreads();

        // edge-input A-frags for this warp (reused across all ks)
        int rowL = m0 + r, rowH = rowL + 8;
        uint32_t eh0 = AHK[rowL*4 + q], eh1 = AHK[rowH*4 + q];
        uint32_t el0 = ALK[rowL*4 + q], el1 = ALK[rowH*4 + q];

        // GEMM2 acc init with bias
        float acc[12][4];
        #pragma unroll
        for (int nt = 0; nt < 12; nt++) {
            float2 bb = *(const float2*)&b2s[nt*8 + q*2];
            acc[nt][0] = bb.x; acc[nt][1] = bb.y;
            acc[nt][2] = bb.x; acc[nt][3] = bb.y;
        }

        #pragma unroll
        for (int ks = 0; ks < 4; ks++) {
            // MLP1 (3-pass split m16n8k8) for hidden n-tiles 2ks, 2ks+1
            uint32_t ah[4], al[4];
            #pragma unroll
            for (int h2 = 0; h2 < 2; h2++) {
                int nt1 = 2*ks + h2;
                float2 bb = *(const float2*)&b1s[nt1*8 + q*2];
                float d[4] = { bb.x, bb.y, bb.x, bb.y };
                mma16808(d, eh0, eh1, w1h[nt1]);
                mma16808(d, eh0, eh1, w1l[nt1]);
                mma16808(d, el0, el1, w1h[nt1]);
                float v0 = elu_fast(d[0]), v1 = elu_fast(d[1]);
                float v2 = elu_fast(d[2]), v3 = elu_fast(d[3]);
                split2(v0, v1, ah[h2*2+0], al[h2*2+0]);   // (r,   k2 / k2+4)
                split2(v2, v3, ah[h2*2+1], al[h2*2+1]);   // (r+8, k2 / k2+4)
            }
            // GEMM2 over 12 n-tiles (3-pass split m16n8k16)
            int k2 = ks*8 + q;
            #pragma unroll
            for (int nt = 0; nt < 12; nt++) {
                int bi = (nt*8 + r)*36 + k2;
                uint32_t bh[2] = { BH32[bi], BH32[bi+4] };
                uint32_t bl[2] = { BL32[bi], BL32[bi+4] };
                mma16816(acc[nt], ah, bh);
                mma16816(acc[nt], ah, bl);
                mma16816(acc[nt], al, bh);
            }
        }

        // --- epilogue: interleaved float4 gathers + half-merged RED.128 scatter ---
        {
            int eL = m0 + r, eH = eL + 8;
            int srcL = srcs[eL], srcH = srcs[eH];
            int dstL = dsts[eL], dstH = dsts[eH];
            float uL0 = us[eL*3+0], uL1 = us[eL*3+1], uL2 = us[eL*3+2];
            float uH0 = us[eH*3+0], uH1 = us[eH*3+1], uH2 = us[eH*3+2];
            const float4* svL = g_sv + srcL*Ff;
            const float4* svH = g_sv + srcH*Ff;
            float4* aL = g_acc + dstL*Ff;
            float4* aH = g_acc + dstH*Ff;
            bool merge = (dstL == dstH);
            #pragma unroll
            for (int nt = 0; nt < 4; nt++) {
                int f0 = nt*8 + q*2;
                float4 nL0 = svL[f0], nL1 = svL[f0+1];
                float4 nH0 = svH[f0], nH1 = svH[f0+1];
                float gsL0 = acc[nt  ][0], gsL1 = acc[nt  ][1];
                float gsH0 = acc[nt  ][2], gsH1 = acc[nt  ][3];
                float gvL0 = acc[nt+4][0], gvL1 = acc[nt+4][1];
                float gvH0 = acc[nt+4][2], gvH1 = acc[nt+4][3];
                float gtL0 = acc[nt+8][0], gtL1 = acc[nt+8][1];
                float gtH0 = acc[nt+8][2], gtH1 = acc[nt+8][3];
                float tL0 = gtL0*nL0.x, tL1 = gtL1*nL1.x;
                float tH0 = gtH0*nH0.x, tH1 = gtH1*nH1.x;
                float4 mL0 = make_float4(gsL0*nL0.x, fmaf(gvL0, nL0.y, tL0*uL0),
                                         fmaf(gvL0, nL0.z, tL0*uL1), fmaf(gvL0, nL0.w, tL0*uL2));
                float4 mL1 = make_float4(gsL1*nL1.x, fmaf(gvL1, nL1.y, tL1*uL0),
                                         fmaf(gvL1, nL1.z, tL1*uL1), fmaf(gvL1, nL1.w, tL1*uL2));
                float4 mH0 = make_float4(gsH0*nH0.x, fmaf(gvH0, nH0.y, tH0*uH0),
                                         fmaf(gvH0, nH0.z, tH0*uH1), fmaf(gvH0, nH0.w, tH0*uH2));
                float4 mH1 = make_float4(gsH1*nH1.x, fmaf(gvH1, nH1.y, tH1*uH0),
                                         fmaf(gvH1, nH1.z, tH1*uH1), fmaf(gvH1, nH1.w, tH1*uH2));
                if (merge) {
                    atomicAdd(&aL[f0],   make_float4(mL0.x+mH0.x, mL0.y+mH0.y, mL0.z+mH0.z, mL0.w+mH0.w));
                    atomicAdd(&aL[f0+1], make_float4(mL1.x+mH1.x, mL1.y+mH1.y, mL1.z+mH1.z, mL1.w+mH1.w));
                } else {
                    atomicAdd(&aL[f0],   mL0);
                    atomicAdd(&aL[f0+1], mL1);
                    atomicAdd(&aH[f0],   mH0);
                    atomicAdd(&aH[f0+1], mH1);
                }
            }
        }
    }
}

// ---------------- per-layer node update: residual s,v (+ optional acc reset) ----------------
__global__ void k_update(const float* __restrict__ Ws, const float* __restrict__ Wv, int reset) {
    __shared__ float  wss[1024], wvs[1024];
    __shared__ float4 msh[4][32];
    int tid = threadIdx.x;
    for (int i = tid; i < 1024; i += 128) { wss[i] = Ws[i]; wvs[i] = Wv[i]; }
    __syncthreads();
    int w = tid >> 5, lane = tid & 31;
    int node = blockIdx.x*4 + w;
    if (node >= Nn) return;
    float invd = 1.f / fmaxf((float)g_deg[node], 1.f);
    float4 a = g_acc[node*Ff + lane];
    if (reset) g_acc[node*Ff + lane] = make_float4(0.f,0.f,0.f,0.f);
    msh[w][lane] = make_float4(a.x*invd, a.y*invd, a.z*invd, a.w*invd);
    __syncwarp();
    float so = 0.f, v0 = 0.f, v1 = 0.f, v2 = 0.f;
    #pragma unroll
    for (int f = 0; f < 32; f++) {
        float4 m = msh[w][f];
        float wsv = wss[f*32 + lane];
        float wvv = wvs[f*32 + lane];
        so += m.x*wsv;
        v0 += m.y*wvv; v1 += m.z*wvv; v2 += m.w*wvv;
    }
    int i = node*Ff + lane;
    float4 sv = g_sv[i];
    sv.x += elu1(so);
    sv.y += v0; sv.z += v1; sv.w += v2;
    g_sv[i] = sv;
}

// ---------------- invariant map + graph pooling (atomic; gcnt folded) ----------------
__global__ void k_inv(const float* __restrict__ W_inv, const float* __restrict__ b_inv,
                      const int* __restrict__ batch) {
    __shared__ float wi[64*128];
    __shared__ float bi[128];
    __shared__ float feat[4][64];
    int tid = threadIdx.x;
    for (int i = tid; i < 64*128; i += 128) wi[i] = W_inv[i];
    if (tid < 128) bi[tid] = b_inv[tid];
    __syncthreads();
    int w = tid >> 5, lane = tid & 31;
    int nwarps = gridDim.x*4;
    for (int node = blockIdx.x*4 + w; node < Nn; node += nwarps) {
        float4 sv = g_sv[node*Ff + lane];
        float vn = sqrtf(sv.y*sv.y + sv.z*sv.z + sv.w*sv.w + EPSf);
        feat[w][lane]      = sv.x;
        feat[w][32 + lane] = vn;
        __syncwarp();
        int b = batch[node];
        if (lane == 0) atomicAdd(&g_gcnt[b], 1.f);
        #pragma unroll
        for (int rr = 0; rr < 4; rr++) {
            int c = lane + 32*rr;
            float acc = bi[c];
            #pragma unroll 8
            for (int k = 0; k < 64; k++) acc += feat[w][k] * wi[k*128 + c];
            atomicAdd(&g_xg[b*NINVc + c], acc);
        }
        __syncwarp();
    }
}

// ---------------- head ----------------
__global__ void k_pool_bn1() {
    __shared__ float ssum[256], ssq[256];
    int c = blockIdx.x, tid = threadIdx.x;
    float s = 0.f, q = 0.f;
    for (int g = tid; g < Gc; g += 256) {
        float val = g_xg[g*NINVc + c] / fmaxf(g_gcnt[g], 1.f);
        g_xgp[g*NINVc + c] = val;
        s += val; q += val*val;
    }
    ssum[tid] = s; ssq[tid] = q; __syncthreads();
    for (int st = 128; st > 0; st >>= 1) {
        if (tid < st) { ssum[tid] += ssum[tid+st]; ssq[tid] += ssq[tid+st]; }
        __syncthreads();
    }
    if (tid == 0) {
        float m = ssum[0] / (float)Gc;
        float var = ssq[0] / (float)Gc - m*m;
        g_mean1[c] = m;
        g_rstd1[c] = rsqrtf(var + 1e-5f);
    }
}
__global__ void k_fc1(const float* __restrict__ g1, const float* __restrict__ be1,
                      const float* __restrict__ Wf1, const float* __restrict__ bf1) {
    __shared__ float a[128];
    int g = blockIdx.x, j = threadIdx.x;
    float xv = g_xgp[g*NINVc + j];
    a[j] = elu1((xv - g_mean1[j]) * g_rstd1[j] * g1[j] + be1[j]);
    __syncthreads();
    float acc = bf1[j];
    #pragma unroll 8
    for (int k = 0; k < 128; k++) acc += a[k] * Wf1[k*128 + j];
    g_z1[g*NINVc + j] = acc;
}
__global__ void k_bn2() {
    __shared__ float ssum[256], ssq[256];
    int c = blockIdx.x, tid = threadIdx.x;
    float s = 0.f, q = 0.f;
    for (int g = tid; g < Gc; g += 256) {
        float val = g_z1[g*NINVc + c];
        s += val; q += val*val;
    }
    ssum[tid] = s; ssq[tid] = q; __syncthreads();
    for (int st = 128; st > 0; st >>= 1) {
        if (tid < st) { ssum[tid] += ssum[tid+st]; ssq[tid] += ssq[tid+st]; }
        __syncthreads();
    }
    if (tid == 0) {
        float m = ssum[0] / (float)Gc;
        float var = ssq[0] / (float)Gc - m*m;
        g_mean2[c] = m;
        g_rstd2[c] = rsqrtf(var + 1e-5f);
    }
}
__global__ void k_head(const float* __restrict__ g2, const float* __restrict__ be2,
                       const float* __restrict__ Wf2, const float* __restrict__ bf2,
                       float* __restrict__ out) {
    int w = threadIdx.x >> 5, lane = threadIdx.x & 31;
    int g = blockIdx.x*4 + w;
    if (g >= Gc) return;
    float p = 0.f;
    for (int k = lane; k < 128; k += 32) {
        float zv = g_z1[g*NINVc + k];
        float av = elu1((zv - g_mean2[k]) * g_rstd2[k] * g2[k] + be2[k]);
        p += av * Wf2[k];
    }
    #pragma unroll
    for (int off = 16; off; off >>= 1) p += __shfl_down_sync(0xffffffffu, p, off);
    if (lane == 0) out[g] = p + bf2[0];
}

// ---------------- launch ----------------
extern "C" void kernel_launch(void* const* d_in, const int* in_sizes, int n_in,
                              void* d_out, int out_size) {
    const float* x     = (const float*)d_in[0];
    const float* pos   = (const float*)d_in[1];
    const int*   ei    = (const int*)d_in[2];     // int32 (JAX x64 disabled)
    const float* eattr = (const float*)d_in[3];
    const int*   batch = (const int*)d_in[4];     // int32
    const float* W_es  = (const float*)d_in[5];
    const float* b_es  = (const float*)d_in[6];
    const float* W_ev  = (const float*)d_in[7];
    const float* W1    = (const float*)d_in[8];
    const float* b1    = (const float*)d_in[9];
    const float* W2    = (const float*)d_in[10];
    const float* b2    = (const float*)d_in[11];
    const float* Ws    = (const float*)d_in[12];
    const float* Wv    = (const float*)d_in[13];
    const float* W_inv = (const float*)d_in[14];
    const float* b_inv = (const float*)d_in[15];
    const float* g1    = (const float*)d_in[16];
    const float* be1   = (const float*)d_in[17];
    const float* Wf1   = (const float*)d_in[18];
    const float* bf1   = (const float*)d_in[19];
    const float* g2    = (const float*)d_in[20];
    const float* be2   = (const float*)d_in[21];
    const float* Wf2   = (const float*)d_in[22];
    const float* bf2   = (const float*)d_in[23];
    float* out = (float*)d_out;

    cudaFuncSetAttribute(k_msg_mma, cudaFuncAttributeMaxDynamicSharedMemorySize, TC_SMEM);

    int ztotal = Nn*Ff + Nn + Gc + Gc*NINVc;
    k_zero_embed<<<(ztotal + 255)/256, 256>>>(x, pos, W_es, b_es, W_ev);   // #1
    k_hist<<<(Ee + 255)/256, 256>>>(ei);                                   // #2
    k_scan<<<1, 1024>>>();                                                 // #3
    k_edge_prep<<<(Ee + 255)/256, 256>>>(pos, ei, eattr);                  // #4

    for (int l = 0; l < NLc; l++) {
        k_msg_mma<<<444, 256, TC_SMEM>>>(W1 + l*5*Hc, b1 + l*Hc,
                                         W2 + l*Hc*3*Ff, b2 + l*3*Ff);
        k_update<<<Nn/4, 128>>>(Ws + l*Ff*Ff, Wv + l*Ff*Ff, (l < NLc-1) ? 1 : 0);
    }

    k_inv<<<1024, 128>>>(W_inv, b_inv, batch);
    k_pool_bn1<<<NINVc, 256>>>();
    k_fc1<<<Gc, 128>>>(g1, be1, Wf1, bf1);
    k_bn2<<<NINVc, 256>>>();
    k_head<<<Gc/4, 128>>>(g2, be2, Wf2, bf2, out);
}

// round 16
// speedup vs baseline: 1.5645x; 1.1496x over previous
#include <cuda_runtime.h>
#include <cuda_bf16.h>
#include <math.h>
#include <cstdint>

#define Nn   50000
#define Ee   800000
#define Ff   32
#define NINVc 128
#define NLc  4
#define Hc   64
#define Gc   2048
#define EPSf 1e-6f
#define NT   (Ee/128)   // 6250 tiles of 128 edges

// ---------------- device scratch (no allocs allowed) ----------------
__device__ __align__(16) uint32_t g_ein_pk[Ee*8];  // dst-sorted, pre-split edge inputs (hi[4],lo[4])
__device__ float  g_u[Ee*3];                       // dst-sorted
__device__ int    g_src[Ee];                       // dst-sorted
__device__ int    g_dst[Ee];                       // dst-sorted
__device__ float4 g_sv[Nn*Ff];        // {s, v0, v1, v2} interleaved node state
__device__ float4 g_acc[Nn*Ff];       // {ms, mv0, mv1, mv2}
__device__ int    g_deg[Nn];
__device__ int    g_woff[Nn];
__device__ float  g_xg[Gc*NINVc];
__device__ float  g_gcnt[Gc];
__device__ float  g_xgp[Gc*NINVc];
__device__ float  g_z1[Gc*NINVc];
__device__ float  g_mean1[NINVc], g_rstd1[NINVc], g_mean2[NINVc], g_rstd2[NINVc];

__device__ __forceinline__ float elu1(float x) { return x > 0.f ? x : expm1f(x); }
__device__ __forceinline__ float elu_fast(float x) { return x > 0.f ? x : (__expf(x) - 1.f); }

// warp-level bf16 mma (sm_80+ baseline PTX; works on plain sm_103 target)
__device__ __forceinline__ void mma16816(float* d, const uint32_t* a, const uint32_t* b) {
    asm volatile(
        "mma.sync.aligned.m16n8k16.row.col.f32.bf16.bf16.f32 "
        "{%0,%1,%2,%3}, {%4,%5,%6,%7}, {%8,%9}, {%0,%1,%2,%3};"
        : "+f"(d[0]), "+f"(d[1]), "+f"(d[2]), "+f"(d[3])
        : "r"(a[0]), "r"(a[1]), "r"(a[2]), "r"(a[3]), "r"(b[0]), "r"(b[1]));
}
__device__ __forceinline__ void mma16808(float* d, uint32_t a0, uint32_t a1, uint32_t b) {
    asm volatile(
        "mma.sync.aligned.m16n8k8.row.col.f32.bf16.bf16.f32 "
        "{%0,%1,%2,%3}, {%4,%5}, {%6}, {%0,%1,%2,%3};"
        : "+f"(d[0]), "+f"(d[1]), "+f"(d[2]), "+f"(d[3])
        : "r"(a0), "r"(a1), "r"(b));
}
__device__ __forceinline__ void bf16split(float x, uint16_t& h, uint16_t& l) {
    __nv_bfloat16 hb = __float2bfloat16_rn(x);
    float r = x - __bfloat162float(hb);
    __nv_bfloat16 lb = __float2bfloat16_rn(r);
    h = __bfloat16_as_ushort(hb);
    l = __bfloat16_as_ushort(lb);
}
// packed split of (x0, x1) -> hi u32 {bf16(x1),bf16(x0)} and lo u32 of residuals
__device__ __forceinline__ void split2(float x0, float x1, uint32_t& h, uint32_t& l) {
    uint32_t hp;
    asm("cvt.rn.satfinite.bf16x2.f32 %0, %1, %2;" : "=r"(hp) : "f"(x1), "f"(x0));
    float f0 = __uint_as_float(hp << 16);
    float f1 = __uint_as_float(hp & 0xffff0000u);
    float r0 = x0 - f0, r1 = x1 - f1;
    uint32_t lp;
    asm("cvt.rn.satfinite.bf16x2.f32 %0, %1, %2;" : "=r"(lp) : "f"(r1), "f"(r0));
    h = hp; l = lp;
}

// ---------------- #1: zero + embedding fused ----------------
__global__ void k_zero_embed(const float* __restrict__ x, const float* __restrict__ pos,
                             const float* __restrict__ W_es, const float* __restrict__ b_es,
                             const float* __restrict__ W_ev) {
    int i = blockIdx.x*blockDim.x + threadIdx.x;
    if (i < Nn*Ff) {
        g_acc[i] = make_float4(0.f,0.f,0.f,0.f);
        int n = i >> 5, f = i & 31;
        const float* xr = x + n*5;
        float s = b_es[f], ev = 0.f;
        #pragma unroll
        for (int k = 0; k < 5; k++) {
            float xv = xr[k];
            s  += xv * W_es[k*Ff + f];
            ev += xv * W_ev[k*Ff + f];
        }
        float p0 = pos[n*3+0], p1 = pos[n*3+1], p2 = pos[n*3+2];
        g_sv[i] = make_float4(s, ev*p0, ev*p1, ev*p2);
        return;
    }
    i -= Nn*Ff;
    if (i < Nn) { g_deg[i] = 0; return; }
    i -= Nn;
    if (i < Gc) { g_gcnt[i] = 0.f; return; }
    i -= Gc;
    if (i < Gc*NINVc) g_xg[i] = 0.f;
}

// ---------------- #2: dst histogram ----------------
__global__ void k_hist(const int* __restrict__ ei) {
    int e = blockIdx.x*blockDim.x + threadIdx.x;
    if (e < Ee) atomicAdd(&g_deg[ei[Ee + e]], 1);
}

// ---------------- #3: exclusive scan of degrees -> write cursors ----------------
__global__ void k_scan() {
    __shared__ int part[1024];
    int t = threadIdx.x;
    const int per = (Nn + 1023) / 1024;   // 49
    int lo = t*per, hi = min(lo + per, Nn);
    int s = 0;
    for (int i = lo; i < hi; i++) s += g_deg[i];
    part[t] = s;
    __syncthreads();
    for (int off = 1; off < 1024; off <<= 1) {
        int v = (t >= off) ? part[t - off] : 0;
        __syncthreads();
        part[t] += v;
        __syncthreads();
    }
    int run = part[t] - s;   // exclusive prefix
    for (int i = lo; i < hi; i++) { g_woff[i] = run; run += g_deg[i]; }
}

// ---------------- #4: edge prep, pre-split bf16 hi/lo, dst-sorted slots ----------------
__global__ void k_edge_prep(const float* __restrict__ pos,
                            const int* __restrict__ ei,
                            const float* __restrict__ eattr) {
    int e = blockIdx.x*blockDim.x + threadIdx.x;
    if (e >= Ee) return;
    int src = ei[e];
    int dst = ei[Ee + e];
    float dx = pos[dst*3+0] - pos[src*3+0];
    float dy = pos[dst*3+1] - pos[src*3+1];
    float dz = pos[dst*3+2] - pos[src*3+2];
    float d  = sqrtf(dx*dx + dy*dy + dz*dz + EPSf);
    float inv = 1.0f/d;
    int slot = atomicAdd(&g_woff[dst], 1);
    float ea0 = eattr[e*4+0], ea1 = eattr[e*4+1], ea2 = eattr[e*4+2], ea3 = eattr[e*4+3];
    uint32_t ph0,pl0, ph1,pl1, ph2,pl2;
    split2(d,   ea0, ph0, pl0);
    split2(ea1, ea2, ph1, pl1);
    split2(ea3, 0.f, ph2, pl2);
    ((uint4*)g_ein_pk)[slot*2]   = make_uint4(ph0, ph1, ph2, 0u);
    ((uint4*)g_ein_pk)[slot*2+1] = make_uint4(pl0, pl1, pl2, 0u);
    g_u[slot*3+0] = dx*inv;
    g_u[slot*3+1] = dy*inv;
    g_u[slot*3+2] = dz*inv;
    g_src[slot] = src;
    g_dst[slot] = dst;
}

// ---------------- HMMA fused message kernel: MLP1 (m16n8k8) -> GEMM2 (m16n8k16) in regs ----
// Tile = 128 edges, 256 threads (8 warps). Warp w owns edges [w*16, w*16+16).
// Edge-input A-frags staged pre-split from gmem; W1 B-frags resident in registers;
// MLP1 D-frags map directly onto GEMM2 A-frags (elu+split in regs, no A smem).
#define OFF_BH   0          // 13824
#define OFF_BL   13824      // 13824
#define OFF_AHK  27648      // 128*4 u32 = 2048
#define OFF_ALK  29696      // 2048
#define OFF_US   31744      // 384 f = 1536
#define OFF_SRC  33280      // 512
#define OFF_DST  33792      // 512
#define OFF_B1S  34304      // 256
#define OFF_B2S  34560      // 384
#define TC_SMEM  34944
__global__ void __launch_bounds__(256, 2)
k_msg_mma(const float* __restrict__ W1, const float* __restrict__ b1,
          const float* __restrict__ W2, const float* __restrict__ b2) {
    extern __shared__ char smc[];
    uint16_t* BH = (uint16_t*)(smc + OFF_BH);
    uint16_t* BL = (uint16_t*)(smc + OFF_BL);
    uint32_t* AHK = (uint32_t*)(smc + OFF_AHK);
    uint32_t* ALK = (uint32_t*)(smc + OFF_ALK);
    float* us  = (float*)(smc + OFF_US);
    int* srcs  = (int*)(smc + OFF_SRC);
    int* dsts  = (int*)(smc + OFF_DST);
    float* b1s = (float*)(smc + OFF_B1S);
    float* b2s = (float*)(smc + OFF_B2S);
    const uint32_t* BH32 = (const uint32_t*)(smc + OFF_BH);
    const uint32_t* BL32 = (const uint32_t*)(smc + OFF_BL);

    int tid = threadIdx.x;
    for (int i = tid; i < 64;  i += 256) b1s[i] = b1[i];
    for (int i = tid; i < 96;  i += 256) b2s[i] = b2[i];
    for (int idx = tid; idx < 96*64; idx += 256) {
        int n = idx >> 6, k = idx & 63;
        uint16_t h, l; bf16split(W2[k*96 + n], h, l);
        BH[n*72 + k] = h;
        BL[n*72 + k] = l;
    }

    int lane = tid & 31, warp = tid >> 5;
    int m0 = warp * 16;
    int r = lane >> 2, q = lane & 3;

    // W1 B-frags (m16n8k8: b = {k=2q,2q+1, n=nt*8+r}), resident in registers
    uint32_t w1h[8], w1l[8];
    {
        int k0 = 2*q, k1 = 2*q + 1;
        #pragma unroll
        for (int nt = 0; nt < 8; nt++) {
            int n = nt*8 + r;
            float x0 = (k0 < 5) ? W1[k0*64 + n] : 0.f;
            float x1 = (k1 < 5) ? W1[k1*64 + n] : 0.f;
            split2(x0, x1, w1h[nt], w1l[nt]);
        }
    }

    for (int tile = blockIdx.x; tile < NT; tile += gridDim.x) {
        __syncthreads();
        int e0 = tile * 128;
        if (tid < 128) {
            const uint4* s4 = ((const uint4*)g_ein_pk) + (e0 + tid)*2;
            *(uint4*)&AHK[tid*4] = s4[0];
            *(uint4*)&ALK[tid*4] = s4[1];
            srcs[tid] = g_src[e0 + tid];
            dsts[tid] = g_dst[e0 + tid];
        }
        for (int i = tid; i < 384; i += 256) us[i] = g_u[e0*3 + i];
        __syncthreads();

        // edge-input A-frags for this warp (reused across all ks)
        int rowL = m0 + r, rowH = rowL + 8;
        uint32_t eh0 = AHK[rowL*4 + q], eh1 = AHK[rowH*4 + q];
        uint32_t el0 = ALK[rowL*4 + q], el1 = ALK[rowH*4 + q];

        // GEMM2 acc init with bias
        float acc[12][4];
        #pragma unroll
        for (int nt = 0; nt < 12; nt++) {
            float2 bb = *(const float2*)&b2s[nt*8 + q*2];
            acc[nt][0] = bb.x; acc[nt][1] = bb.y;
            acc[nt][2] = bb.x; acc[nt][3] = bb.y;
        }

        #pragma unroll
        for (int ks = 0; ks < 4; ks++) {
            // MLP1 (3-pass split m16n8k8) for hidden n-tiles 2ks, 2ks+1
            uint32_t ah[4], al[4];
            #pragma unroll
            for (int h2 = 0; h2 < 2; h2++) {
                int nt1 = 2*ks + h2;
                float2 bb = *(const float2*)&b1s[nt1*8 + q*2];
                float d[4] = { bb.x, bb.y, bb.x, bb.y };
                mma16808(d, eh0, eh1, w1h[nt1]);
                mma16808(d, eh0, eh1, w1l[nt1]);
                mma16808(d, el0, el1, w1h[nt1]);
                float v0 = elu_fast(d[0]), v1 = elu_fast(d[1]);
                float v2 = elu_fast(d[2]), v3 = elu_fast(d[3]);
                split2(v0, v1, ah[h2*2+0], al[h2*2+0]);   // (r,   k2 / k2+4)
                split2(v2, v3, ah[h2*2+1], al[h2*2+1]);   // (r+8, k2 / k2+4)
            }
            // GEMM2 over 12 n-tiles (3-pass split m16n8k16)
            int k2 = ks*8 + q;
            #pragma unroll
            for (int nt = 0; nt < 12; nt++) {
                int bi = (nt*8 + r)*36 + k2;
                uint32_t bh[2] = { BH32[bi], BH32[bi+4] };
                uint32_t bl[2] = { BL32[bi], BL32[bi+4] };
                mma16816(acc[nt], ah, bh);
                mma16816(acc[nt], ah, bl);
                mma16816(acc[nt], al, bh);
            }
        }

        // --- epilogue: interleaved float4 gathers + half-merged RED.128 scatter ---
        {
            int eL = m0 + r, eH = eL + 8;
            int srcL = srcs[eL], srcH = srcs[eH];
            int dstL = dsts[eL], dstH = dsts[eH];
            float uL0 = us[eL*3+0], uL1 = us[eL*3+1], uL2 = us[eL*3+2];
            float uH0 = us[eH*3+0], uH1 = us[eH*3+1], uH2 = us[eH*3+2];
            const float4* svL = g_sv + srcL*Ff;
            const float4* svH = g_sv + srcH*Ff;
            float4* aL = g_acc + dstL*Ff;
            float4* aH = g_acc + dstH*Ff;
            bool merge = (dstL == dstH);
            #pragma unroll
            for (int nt = 0; nt < 4; nt++) {
                int f0 = nt*8 + q*2;
                float4 nL0 = svL[f0], nL1 = svL[f0+1];
                float4 nH0 = svH[f0], nH1 = svH[f0+1];
                float gsL0 = acc[nt  ][0], gsL1 = acc[nt  ][1];
                float gsH0 = acc[nt  ][2], gsH1 = acc[nt  ][3];
                float gvL0 = acc[nt+4][0], gvL1 = acc[nt+4][1];
                float gvH0 = acc[nt+4][2], gvH1 = acc[nt+4][3];
                float gtL0 = acc[nt+8][0], gtL1 = acc[nt+8][1];
                float gtH0 = acc[nt+8][2], gtH1 = acc[nt+8][3];
                float tL0 = gtL0*nL0.x, tL1 = gtL1*nL1.x;
                float tH0 = gtH0*nH0.x, tH1 = gtH1*nH1.x;
                float4 mL0 = make_float4(gsL0*nL0.x, fmaf(gvL0, nL0.y, tL0*uL0),
                                         fmaf(gvL0, nL0.z, tL0*uL1), fmaf(gvL0, nL0.w, tL0*uL2));
                float4 mL1 = make_float4(gsL1*nL1.x, fmaf(gvL1, nL1.y, tL1*uL0),
                                         fmaf(gvL1, nL1.z, tL1*uL1), fmaf(gvL1, nL1.w, tL1*uL2));
                float4 mH0 = make_float4(gsH0*nH0.x, fmaf(gvH0, nH0.y, tH0*uH0),
                                         fmaf(gvH0, nH0.z, tH0*uH1), fmaf(gvH0, nH0.w, tH0*uH2));
                float4 mH1 = make_float4(gsH1*nH1.x, fmaf(gvH1, nH1.y, tH1*uH0),
                                         fmaf(gvH1, nH1.z, tH1*uH1), fmaf(gvH1, nH1.w, tH1*uH2));
                if (merge) {
                    atomicAdd(&aL[f0],   make_float4(mL0.x+mH0.x, mL0.y+mH0.y, mL0.z+mH0.z, mL0.w+mH0.w));
                    atomicAdd(&aL[f0+1], make_float4(mL1.x+mH1.x, mL1.y+mH1.y, mL1.z+mH1.z, mL1.w+mH1.w));
                } else {
                    atomicAdd(&aL[f0],   mL0);
                    atomicAdd(&aL[f0+1], mL1);
                    atomicAdd(&aH[f0],   mH0);
                    atomicAdd(&aH[f0+1], mH1);
                }
            }
        }
    }
}

// ---------------- per-layer node update: residual s,v (+ optional acc reset) ----------------
__global__ void k_update(const float* __restrict__ Ws, const float* __restrict__ Wv, int reset) {
    __shared__ float  wss[1024], wvs[1024];
    __shared__ float4 msh[4][32];
    int tid = threadIdx.x;
    for (int i = tid; i < 1024; i += 128) { wss[i] = Ws[i]; wvs[i] = Wv[i]; }
    __syncthreads();
    int w = tid >> 5, lane = tid & 31;
    int node = blockIdx.x*4 + w;
    if (node >= Nn) return;
    float invd = 1.f / fmaxf((float)g_deg[node], 1.f);
    float4 a = g_acc[node*Ff + lane];
    if (reset) g_acc[node*Ff + lane] = make_float4(0.f,0.f,0.f,0.f);
    msh[w][lane] = make_float4(a.x*invd, a.y*invd, a.z*invd, a.w*invd);
    __syncwarp();
    float so = 0.f, v0 = 0.f, v1 = 0.f, v2 = 0.f;
    #pragma unroll
    for (int f = 0; f < 32; f++) {
        float4 m = msh[w][f];
        float wsv = wss[f*32 + lane];
        float wvv = wvs[f*32 + lane];
        so += m.x*wsv;
        v0 += m.y*wvv; v1 += m.z*wvv; v2 += m.w*wvv;
    }
    int i = node*Ff + lane;
    float4 sv = g_sv[i];
    sv.x += elu1(so);
    sv.y += v0; sv.z += v1; sv.w += v2;
    g_sv[i] = sv;
}

// ---------------- invariant map + graph pooling (atomic; gcnt folded) ----------------
__global__ void k_inv(const float* __restrict__ W_inv, const float* __restrict__ b_inv,
                      const int* __restrict__ batch) {
    __shared__ float wi[64*128];
    __shared__ float bi[128];
    __shared__ float feat[4][64];
    int tid = threadIdx.x;
    for (int i = tid; i < 64*128; i += 128) wi[i] = W_inv[i];
    if (tid < 128) bi[tid] = b_inv[tid];
    __syncthreads();
    int w = tid >> 5, lane = tid & 31;
    int nwarps = gridDim.x*4;
    for (int node = blockIdx.x*4 + w; node < Nn; node += nwarps) {
        float4 sv = g_sv[node*Ff + lane];
        float vn = sqrtf(sv.y*sv.y + sv.z*sv.z + sv.w*sv.w + EPSf);
        feat[w][lane]      = sv.x;
        feat[w][32 + lane] = vn;
        __syncwarp();
        int b = batch[node];
        if (lane == 0) atomicAdd(&g_gcnt[b], 1.f);
        #pragma unroll
        for (int rr = 0; rr < 4; rr++) {
            int c = lane + 32*rr;
            float acc = bi[c];
            #pragma unroll 8
            for (int k = 0; k < 64; k++) acc += feat[w][k] * wi[k*128 + c];
            atomicAdd(&g_xg[b*NINVc + c], acc);
        }
        __syncwarp();
    }
}

// ---------------- head ----------------
__global__ void k_pool_bn1() {
    __shared__ float ssum[256], ssq[256];
    int c = blockIdx.x, tid = threadIdx.x;
    float s = 0.f, q = 0.f;
    for (int g = tid; g < Gc; g += 256) {
        float val = g_xg[g*NINVc + c] / fmaxf(g_gcnt[g], 1.f);
        g_xgp[g*NINVc + c] = val;
        s += val; q += val*val;
    }
    ssum[tid] = s; ssq[tid] = q; __syncthreads();
    for (int st = 128; st > 0; st >>= 1) {
        if (tid < st) { ssum[tid] += ssum[tid+st]; ssq[tid] += ssq[tid+st]; }
        __syncthreads();
    }
    if (tid == 0) {
        float m = ssum[0] / (float)Gc;
        float var = ssq[0] / (float)Gc - m*m;
        g_mean1[c] = m;
        g_rstd1[c] = rsqrtf(var + 1e-5f);
    }
}
__global__ void k_fc1(const float* __restrict__ g1, const float* __restrict__ be1,
                      const float* __restrict__ Wf1, const float* __restrict__ bf1) {
    __shared__ float a[128];
    int g = blockIdx.x, j = threadIdx.x;
    float xv = g_xgp[g*NINVc + j];
    a[j] = elu1((xv - g_mean1[j]) * g_rstd1[j] * g1[j] + be1[j]);
    __syncthreads();
    float acc = bf1[j];
    #pragma unroll 8
    for (int k = 0; k < 128; k++) acc += a[k] * Wf1[k*128 + j];
    g_z1[g*NINVc + j] = acc;
}
__global__ void k_bn2() {
    __shared__ float ssum[256], ssq[256];
    int c = blockIdx.x, tid = threadIdx.x;
    float s = 0.f, q = 0.f;
    for (int g = tid; g < Gc; g += 256) {
        float val = g_z1[g*NINVc + c];
        s += val; q += val*val;
    }
    ssum[tid] = s; ssq[tid] = q; __syncthreads();
    for (int st = 128; st > 0; st >>= 1) {
        if (tid < st) { ssum[tid] += ssum[tid+st]; ssq[tid] += ssq[tid+st]; }
        __syncthreads();
    }
    if (tid == 0) {
        float m = ssum[0] / (float)Gc;
        float var = ssq[0] / (float)Gc - m*m;
        g_mean2[c] = m;
        g_rstd2[c] = rsqrtf(var + 1e-5f);
    }
}
__global__ void k_head(const float* __restrict__ g2, const float* __restrict__ be2,
                       const float* __restrict__ Wf2, const float* __restrict__ bf2,
                       float* __restrict__ out) {
    int w = threadIdx.x >> 5, lane = threadIdx.x & 31;
    int g = blockIdx.x*4 + w;
    if (g >= Gc) return;
    float p = 0.f;
    for (int k = lane; k < 128; k += 32) {
        float zv = g_z1[g*NINVc + k];
        float av = elu1((zv - g_mean2[k]) * g_rstd2[k] * g2[k] + be2[k]);
        p += av * Wf2[k];
    }
    #pragma unroll
    for (int off = 16; off; off >>= 1) p += __shfl_down_sync(0xffffffffu, p, off);
    if (lane == 0) out[g] = p + bf2[0];
}

// ---------------- launch ----------------
extern "C" void kernel_launch(void* const* d_in, const int* in_sizes, int n_in,
                              void* d_out, int out_size) {
    const float* x     = (const float*)d_in[0];
    const float* pos   = (const float*)d_in[1];
    const int*   ei    = (const int*)d_in[2];     // int32 (JAX x64 disabled)
    const float* eattr = (const float*)d_in[3];
    const int*   batch = (const int*)d_in[4];     // int32
    const float* W_es  = (const float*)d_in[5];
    const float* b_es  = (const float*)d_in[6];
    const float* W_ev  = (const float*)d_in[7];
    const float* W1    = (const float*)d_in[8];
    const float* b1    = (const float*)d_in[9];
    const float* W2    = (const float*)d_in[10];
    const float* b2    = (const float*)d_in[11];
    const float* Ws    = (const float*)d_in[12];
    const float* Wv    = (const float*)d_in[13];
    const float* W_inv = (const float*)d_in[14];
    const float* b_inv = (const float*)d_in[15];
    const float* g1    = (const float*)d_in[16];
    const float* be1   = (const float*)d_in[17];
    const float* Wf1   = (const float*)d_in[18];
    const float* bf1   = (const float*)d_in[19];
    const float* g2    = (const float*)d_in[20];
    const float* be2   = (const float*)d_in[21];
    const float* Wf2   = (const float*)d_in[22];
    const float* bf2   = (const float*)d_in[23];
    float* out = (float*)d_out;

    cudaFuncSetAttribute(k_msg_mma, cudaFuncAttributeMaxDynamicSharedMemorySize, TC_SMEM);

    int ztotal = Nn*Ff + Nn + Gc + Gc*NINVc;
    k_zero_embed<<<(ztotal + 255)/256, 256>>>(x, pos, W_es, b_es, W_ev);   // #1
    k_hist<<<(Ee + 255)/256, 256>>>(ei);                                   // #2
    k_scan<<<1, 1024>>>();                                                 // #3
    k_edge_prep<<<(Ee + 255)/256, 256>>>(pos, ei, eattr);                  // #4

    for (int l = 0; l < NLc; l++) {
        k_msg_mma<<<296, 256, TC_SMEM>>>(W1 + l*5*Hc, b1 + l*Hc,
                                         W2 + l*Hc*3*Ff, b2 + l*3*Ff);
        k_update<<<Nn/4, 128>>>(Ws + l*Ff*Ff, Wv + l*Ff*Ff, (l < NLc-1) ? 1 : 0);
    }

    k_inv<<<1024, 128>>>(W_inv, b_inv, batch);
    k_pool_bn1<<<NINVc, 256>>>();
    k_fc1<<<Gc, 128>>>(g1, be1, Wf1, bf1);
    k_bn2<<<NINVc, 256>>>();
    k_head<<<Gc/4, 128>>>(g2, be2, Wf2, bf2, out);
}

// round 17
// speedup vs baseline: 1.6807x; 1.0743x over previous
#include <cuda_runtime.h>
#include <cuda_bf16.h>
#include <math.h>
#include <cstdint>

#define Nn   50000
#define Ee   800000
#define Ff   32
#define NINVc 128
#define NLc  4
#define Hc   64
#define Gc   2048
#define EPSf 1e-6f
#define NT   (Ee/128)   // 6250 tiles of 128 edges

// ---------------- device scratch (no allocs allowed) ----------------
__device__ __align__(16) uint32_t g_ein_pk[Ee*8];  // dst-sorted, pre-split edge inputs (hi[4],lo[4])
__device__ float  g_u[Ee*3];                       // dst-sorted
__device__ int    g_src[Ee];                       // dst-sorted
__device__ int    g_dst[Ee];                       // dst-sorted
__device__ float4 g_sv[Nn*Ff];        // {s, v0, v1, v2} interleaved node state
__device__ float4 g_acc[Nn*Ff];       // {ms, mv0, mv1, mv2}
__device__ int    g_deg[Nn];
__device__ int    g_woff[Nn];
__device__ float  g_xg[Gc*NINVc];
__device__ float  g_gcnt[Gc];
__device__ float  g_xgp[Gc*NINVc];
__device__ float  g_z1[Gc*NINVc];
__device__ float  g_mean1[NINVc], g_rstd1[NINVc], g_mean2[NINVc], g_rstd2[NINVc];

__device__ __forceinline__ float elu1(float x) { return x > 0.f ? x : expm1f(x); }
__device__ __forceinline__ float elu_fast(float x) { return x > 0.f ? x : (__expf(x) - 1.f); }

// warp-level bf16 mma (sm_80+ baseline PTX; works on plain sm_103 target)
__device__ __forceinline__ void mma16816(float* d, const uint32_t* a, const uint32_t* b) {
    asm volatile(
        "mma.sync.aligned.m16n8k16.row.col.f32.bf16.bf16.f32 "
        "{%0,%1,%2,%3}, {%4,%5,%6,%7}, {%8,%9}, {%0,%1,%2,%3};"
        : "+f"(d[0]), "+f"(d[1]), "+f"(d[2]), "+f"(d[3])
        : "r"(a[0]), "r"(a[1]), "r"(a[2]), "r"(a[3]), "r"(b[0]), "r"(b[1]));
}
__device__ __forceinline__ void mma16808(float* d, uint32_t a0, uint32_t a1, uint32_t b) {
    asm volatile(
        "mma.sync.aligned.m16n8k8.row.col.f32.bf16.bf16.f32 "
        "{%0,%1,%2,%3}, {%4,%5}, {%6}, {%0,%1,%2,%3};"
        : "+f"(d[0]), "+f"(d[1]), "+f"(d[2]), "+f"(d[3])
        : "r"(a0), "r"(a1), "r"(b));
}
__device__ __forceinline__ void bf16split(float x, uint16_t& h, uint16_t& l) {
    __nv_bfloat16 hb = __float2bfloat16_rn(x);
    float r = x - __bfloat162float(hb);
    __nv_bfloat16 lb = __float2bfloat16_rn(r);
    h = __bfloat16_as_ushort(hb);
    l = __bfloat16_as_ushort(lb);
}
// packed split of (x0, x1) -> hi u32 {bf16(x1),bf16(x0)} and lo u32 of residuals
__device__ __forceinline__ void split2(float x0, float x1, uint32_t& h, uint32_t& l) {
    uint32_t hp;
    asm("cvt.rn.satfinite.bf16x2.f32 %0, %1, %2;" : "=r"(hp) : "f"(x1), "f"(x0));
    float f0 = __uint_as_float(hp << 16);
    float f1 = __uint_as_float(hp & 0xffff0000u);
    float r0 = x0 - f0, r1 = x1 - f1;
    uint32_t lp;
    asm("cvt.rn.satfinite.bf16x2.f32 %0, %1, %2;" : "=r"(lp) : "f"(r1), "f"(r0));
    h = hp; l = lp;
}

// ---------------- #1: zero + embedding fused ----------------
__global__ void k_zero_embed(const float* __restrict__ x, const float* __restrict__ pos,
                             const float* __restrict__ W_es, const float* __restrict__ b_es,
                             const float* __restrict__ W_ev) {
    int i = blockIdx.x*blockDim.x + threadIdx.x;
    if (i < Nn*Ff) {
        g_acc[i] = make_float4(0.f,0.f,0.f,0.f);
        int n = i >> 5, f = i & 31;
        const float* xr = x + n*5;
        float s = b_es[f], ev = 0.f;
        #pragma unroll
        for (int k = 0; k < 5; k++) {
            float xv = xr[k];
            s  += xv * W_es[k*Ff + f];
            ev += xv * W_ev[k*Ff + f];
        }
        float p0 = pos[n*3+0], p1 = pos[n*3+1], p2 = pos[n*3+2];
        g_sv[i] = make_float4(s, ev*p0, ev*p1, ev*p2);
        return;
    }
    i -= Nn*Ff;
    if (i < Nn) { g_deg[i] = 0; return; }
    i -= Nn;
    if (i < Gc) { g_gcnt[i] = 0.f; return; }
    i -= Gc;
    if (i < Gc*NINVc) g_xg[i] = 0.f;
}

// ---------------- #2: dst histogram ----------------
__global__ void k_hist(const int* __restrict__ ei) {
    int e = blockIdx.x*blockDim.x + threadIdx.x;
    if (e < Ee) atomicAdd(&g_deg[ei[Ee + e]], 1);
}

// ---------------- #3: exclusive scan of degrees -> write cursors ----------------
__global__ void k_scan() {
    __shared__ int part[1024];
    int t = threadIdx.x;
    const int per = (Nn + 1023) / 1024;   // 49
    int lo = t*per, hi = min(lo + per, Nn);
    int s = 0;
    for (int i = lo; i < hi; i++) s += g_deg[i];
    part[t] = s;
    __syncthreads();
    for (int off = 1; off < 1024; off <<= 1) {
        int v = (t >= off) ? part[t - off] : 0;
        __syncthreads();
        part[t] += v;
        __syncthreads();
    }
    int run = part[t] - s;   // exclusive prefix
    for (int i = lo; i < hi; i++) { g_woff[i] = run; run += g_deg[i]; }
}

// ---------------- #4: edge prep, pre-split bf16 hi/lo, dst-sorted slots ----------------
__global__ void k_edge_prep(const float* __restrict__ pos,
                            const int* __restrict__ ei,
                            const float* __restrict__ eattr) {
    int e = blockIdx.x*blockDim.x + threadIdx.x;
    if (e >= Ee) return;
    int src = ei[e];
    int dst = ei[Ee + e];
    float dx = pos[dst*3+0] - pos[src*3+0];
    float dy = pos[dst*3+1] - pos[src*3+1];
    float dz = pos[dst*3+2] - pos[src*3+2];
    float d  = sqrtf(dx*dx + dy*dy + dz*dz + EPSf);
    float inv = 1.0f/d;
    int slot = atomicAdd(&g_woff[dst], 1);
    float ea0 = eattr[e*4+0], ea1 = eattr[e*4+1], ea2 = eattr[e*4+2], ea3 = eattr[e*4+3];
    uint32_t ph0,pl0, ph1,pl1, ph2,pl2;
    split2(d,   ea0, ph0, pl0);
    split2(ea1, ea2, ph1, pl1);
    split2(ea3, 0.f, ph2, pl2);
    ((uint4*)g_ein_pk)[slot*2]   = make_uint4(ph0, ph1, ph2, 0u);
    ((uint4*)g_ein_pk)[slot*2+1] = make_uint4(pl0, pl1, pl2, 0u);
    g_u[slot*3+0] = dx*inv;
    g_u[slot*3+1] = dy*inv;
    g_u[slot*3+2] = dz*inv;
    g_src[slot] = src;
    g_dst[slot] = dst;
}

// ---------------- HMMA fused message kernel: MLP1 (m16n8k8) -> GEMM2 (m16n8k16) in regs ----
// Tile = 128 edges, 256 threads (8 warps). Warp w owns sorted edges [w*16, w*16+16),
// PERMUTED into fragment rows so thread (r,q) holds ADJACENT sorted edges (2r, 2r+1):
//   sorted-local j -> row (j>>1) + (j&1)*8. With dst-sorted edges (avg degree 16),
//   dstL==dstH ~94% of the time -> half-merged RED.128 scatter mostly fires.
#define OFF_BH   0          // 13824
#define OFF_BL   13824      // 13824
#define OFF_AHK  27648      // 128*4 u32 = 2048
#define OFF_ALK  29696      // 2048
#define OFF_US   31744      // 384 f = 1536
#define OFF_SRC  33280      // 512
#define OFF_DST  33792      // 512
#define OFF_B1S  34304      // 256
#define OFF_B2S  34560      // 384
#define TC_SMEM  34944
__global__ void __launch_bounds__(256, 2)
k_msg_mma(const float* __restrict__ W1, const float* __restrict__ b1,
          const float* __restrict__ W2, const float* __restrict__ b2) {
    extern __shared__ char smc[];
    uint16_t* BH = (uint16_t*)(smc + OFF_BH);
    uint16_t* BL = (uint16_t*)(smc + OFF_BL);
    uint32_t* AHK = (uint32_t*)(smc + OFF_AHK);
    uint32_t* ALK = (uint32_t*)(smc + OFF_ALK);
    float* us  = (float*)(smc + OFF_US);
    int* srcs  = (int*)(smc + OFF_SRC);
    int* dsts  = (int*)(smc + OFF_DST);
    float* b1s = (float*)(smc + OFF_B1S);
    float* b2s = (float*)(smc + OFF_B2S);
    const uint32_t* BH32 = (const uint32_t*)(smc + OFF_BH);
    const uint32_t* BL32 = (const uint32_t*)(smc + OFF_BL);

    int tid = threadIdx.x;
    for (int i = tid; i < 64;  i += 256) b1s[i] = b1[i];
    for (int i = tid; i < 96;  i += 256) b2s[i] = b2[i];
    for (int idx = tid; idx < 96*64; idx += 256) {
        int n = idx >> 6, k = idx & 63;
        uint16_t h, l; bf16split(W2[k*96 + n], h, l);
        BH[n*72 + k] = h;
        BL[n*72 + k] = l;
    }

    int lane = tid & 31, warp = tid >> 5;
    int m0 = warp * 16;
    int r = lane >> 2, q = lane & 3;

    // W1 B-frags (m16n8k8: b = {k=2q,2q+1, n=nt*8+r}), resident in registers
    uint32_t w1h[8], w1l[8];
    {
        int k0 = 2*q, k1 = 2*q + 1;
        #pragma unroll
        for (int nt = 0; nt < 8; nt++) {
            int n = nt*8 + r;
            float x0 = (k0 < 5) ? W1[k0*64 + n] : 0.f;
            float x1 = (k1 < 5) ? W1[k1*64 + n] : 0.f;
            split2(x0, x1, w1h[nt], w1l[nt]);
        }
    }

    for (int tile = blockIdx.x; tile < NT; tile += gridDim.x) {
        __syncthreads();
        int e0 = tile * 128;
        if (tid < 128) {
            // sorted-local j within warp-tile -> fragment row (pair-adjacent mapping)
            int wlocal = tid >> 4, j = tid & 15;
            int row = wlocal*16 + (j >> 1) + (j & 1)*8;
            const uint4* s4 = ((const uint4*)g_ein_pk) + (e0 + tid)*2;
            *(uint4*)&AHK[row*4] = s4[0];
            *(uint4*)&ALK[row*4] = s4[1];
            srcs[tid] = g_src[e0 + tid];   // sorted order
            dsts[tid] = g_dst[e0 + tid];
        }
        for (int i = tid; i < 384; i += 256) us[i] = g_u[e0*3 + i];
        __syncthreads();

        // edge-input A-frags for this warp (reused across all ks)
        int rowL = m0 + r, rowH = rowL + 8;
        uint32_t eh0 = AHK[rowL*4 + q], eh1 = AHK[rowH*4 + q];
        uint32_t el0 = ALK[rowL*4 + q], el1 = ALK[rowH*4 + q];

        // GEMM2 acc init with bias
        float acc[12][4];
        #pragma unroll
        for (int nt = 0; nt < 12; nt++) {
            float2 bb = *(const float2*)&b2s[nt*8 + q*2];
            acc[nt][0] = bb.x; acc[nt][1] = bb.y;
            acc[nt][2] = bb.x; acc[nt][3] = bb.y;
        }

        #pragma unroll
        for (int ks = 0; ks < 4; ks++) {
            // MLP1 (3-pass split m16n8k8) for hidden n-tiles 2ks, 2ks+1
            uint32_t ah[4], al[4];
            #pragma unroll
            for (int h2 = 0; h2 < 2; h2++) {
                int nt1 = 2*ks + h2;
                float2 bb = *(const float2*)&b1s[nt1*8 + q*2];
                float d[4] = { bb.x, bb.y, bb.x, bb.y };
                mma16808(d, eh0, eh1, w1h[nt1]);
                mma16808(d, eh0, eh1, w1l[nt1]);
                mma16808(d, el0, el1, w1h[nt1]);
                float v0 = elu_fast(d[0]), v1 = elu_fast(d[1]);
                float v2 = elu_fast(d[2]), v3 = elu_fast(d[3]);
                split2(v0, v1, ah[h2*2+0], al[h2*2+0]);   // (r,   k2 / k2+4)
                split2(v2, v3, ah[h2*2+1], al[h2*2+1]);   // (r+8, k2 / k2+4)
            }
            // GEMM2 over 12 n-tiles (3-pass split m16n8k16)
            int k2 = ks*8 + q;
            #pragma unroll
            for (int nt = 0; nt < 12; nt++) {
                int bi = (nt*8 + r)*36 + k2;
                uint32_t bh[2] = { BH32[bi], BH32[bi+4] };
                uint32_t bl[2] = { BL32[bi], BL32[bi+4] };
                mma16816(acc[nt], ah, bh);
                mma16816(acc[nt], ah, bl);
                mma16816(acc[nt], al, bh);
            }
        }

        // --- epilogue: rows (r, r+8) = sorted edges (2r, 2r+1) -> merged scatter ~94% ---
        {
            int jL = m0 + 2*r, jH = jL + 1;      // sorted indices for rows rowL, rowH
            int srcL = srcs[jL], srcH = srcs[jH];
            int dstL = dsts[jL], dstH = dsts[jH];
            float uL0 = us[jL*3+0], uL1 = us[jL*3+1], uL2 = us[jL*3+2];
            float uH0 = us[jH*3+0], uH1 = us[jH*3+1], uH2 = us[jH*3+2];
            const float4* svL = g_sv + srcL*Ff;
            const float4* svH = g_sv + srcH*Ff;
            float4* aL = g_acc + dstL*Ff;
            float4* aH = g_acc + dstH*Ff;
            bool merge = (dstL == dstH);
            #pragma unroll
            for (int nt = 0; nt < 4; nt++) {
                int f0 = nt*8 + q*2;
                float4 nL0 = svL[f0], nL1 = svL[f0+1];
                float4 nH0 = svH[f0], nH1 = svH[f0+1];
                float gsL0 = acc[nt  ][0], gsL1 = acc[nt  ][1];
                float gsH0 = acc[nt  ][2], gsH1 = acc[nt  ][3];
                float gvL0 = acc[nt+4][0], gvL1 = acc[nt+4][1];
                float gvH0 = acc[nt+4][2], gvH1 = acc[nt+4][3];
                float gtL0 = acc[nt+8][0], gtL1 = acc[nt+8][1];
                float gtH0 = acc[nt+8][2], gtH1 = acc[nt+8][3];
                float tL0 = gtL0*nL0.x, tL1 = gtL1*nL1.x;
                float tH0 = gtH0*nH0.x, tH1 = gtH1*nH1.x;
                float4 mL0 = make_float4(gsL0*nL0.x, fmaf(gvL0, nL0.y, tL0*uL0),
                                         fmaf(gvL0, nL0.z, tL0*uL1), fmaf(gvL0, nL0.w, tL0*uL2));
                float4 mL1 = make_float4(gsL1*nL1.x, fmaf(gvL1, nL1.y, tL1*uL0),
                                         fmaf(gvL1, nL1.z, tL1*uL1), fmaf(gvL1, nL1.w, tL1*uL2));
                float4 mH0 = make_float4(gsH0*nH0.x, fmaf(gvH0, nH0.y, tH0*uH0),
                                         fmaf(gvH0, nH0.z, tH0*uH1), fmaf(gvH0, nH0.w, tH0*uH2));
                float4 mH1 = make_float4(gsH1*nH1.x, fmaf(gvH1, nH1.y, tH1*uH0),
                                         fmaf(gvH1, nH1.z, tH1*uH1), fmaf(gvH1, nH1.w, tH1*uH2));
                if (merge) {
                    atomicAdd(&aL[f0],   make_float4(mL0.x+mH0.x, mL0.y+mH0.y, mL0.z+mH0.z, mL0.w+mH0.w));
                    atomicAdd(&aL[f0+1], make_float4(mL1.x+mH1.x, mL1.y+mH1.y, mL1.z+mH1.z, mL1.w+mH1.w));
                } else {
                    atomicAdd(&aL[f0],   mL0);
                    atomicAdd(&aL[f0+1], mL1);
                    atomicAdd(&aH[f0],   mH0);
                    atomicAdd(&aH[f0+1], mH1);
                }
            }
        }
    }
}

// ---------------- per-layer node update: 8 nodes/block, residual s,v (+ optional reset) ----
__global__ void k_update(const float* __restrict__ Ws, const float* __restrict__ Wv, int reset) {
    __shared__ float  wss[1024], wvs[1024];
    __shared__ float4 msh[8][32];
    int tid = threadIdx.x;
    for (int i = tid; i < 1024; i += 256) { wss[i] = Ws[i]; wvs[i] = Wv[i]; }
    __syncthreads();
    int w = tid >> 5, lane = tid & 31;
    int node = blockIdx.x*8 + w;
    if (node >= Nn) return;
    float invd = 1.f / fmaxf((float)g_deg[node], 1.f);
    float4 a = g_acc[node*Ff + lane];
    if (reset) g_acc[node*Ff + lane] = make_float4(0.f,0.f,0.f,0.f);
    msh[w][lane] = make_float4(a.x*invd, a.y*invd, a.z*invd, a.w*invd);
    __syncwarp();
    float so = 0.f, v0 = 0.f, v1 = 0.f, v2 = 0.f;
    #pragma unroll
    for (int f = 0; f < 32; f++) {
        float4 m = msh[w][f];
        float wsv = wss[f*32 + lane];
        float wvv = wvs[f*32 + lane];
        so += m.x*wsv;
        v0 += m.y*wvv; v1 += m.z*wvv; v2 += m.w*wvv;
    }
    int i = node*Ff + lane;
    float4 sv = g_sv[i];
    sv.x += elu1(so);
    sv.y += v0; sv.z += v1; sv.w += v2;
    g_sv[i] = sv;
}

// ---------------- invariant map + graph pooling (atomic; gcnt folded) ----------------
__global__ void k_inv(const float* __restrict__ W_inv, const float* __restrict__ b_inv,
                      const int* __restrict__ batch) {
    __shared__ float wi[64*128];
    __shared__ float bi[128];
    __shared__ float feat[4][64];
    int tid = threadIdx.x;
    for (int i = tid; i < 64*128; i += 128) wi[i] = W_inv[i];
    if (tid < 128) bi[tid] = b_inv[tid];
    __syncthreads();
    int w = tid >> 5, lane = tid & 31;
    int nwarps = gridDim.x*4;
    for (int node = blockIdx.x*4 + w; node < Nn; node += nwarps) {
        float4 sv = g_sv[node*Ff + lane];
        float vn = sqrtf(sv.y*sv.y + sv.z*sv.z + sv.w*sv.w + EPSf);
        feat[w][lane]      = sv.x;
        feat[w][32 + lane] = vn;
        __syncwarp();
        int b = batch[node];
        if (lane == 0) atomicAdd(&g_gcnt[b], 1.f);
        #pragma unroll
        for (int rr = 0; rr < 4; rr++) {
            int c = lane + 32*rr;
            float acc = bi[c];
            #pragma unroll 8
            for (int k = 0; k < 64; k++) acc += feat[w][k] * wi[k*128 + c];
            atomicAdd(&g_xg[b*NINVc + c], acc);
        }
        __syncwarp();
    }
}

// ---------------- head ----------------
__global__ void k_pool_bn1() {
    __shared__ float ssum[256], ssq[256];
    int c = blockIdx.x, tid = threadIdx.x;
    float s = 0.f, q = 0.f;
    for (int g = tid; g < Gc; g += 256) {
        float val = g_xg[g*NINVc + c] / fmaxf(g_gcnt[g], 1.f);
        g_xgp[g*NINVc + c] = val;
        s += val; q += val*val;
    }
    ssum[tid] = s; ssq[tid] = q; __syncthreads();
    for (int st = 128; st > 0; st >>= 1) {
        if (tid < st) { ssum[tid] += ssum[tid+st]; ssq[tid] += ssq[tid+st]; }
        __syncthreads();
    }
    if (tid == 0) {
        float m = ssum[0] / (float)Gc;
        float var = ssq[0] / (float)Gc - m*m;
        g_mean1[c] = m;
        g_rstd1[c] = rsqrtf(var + 1e-5f);
    }
}
__global__ void k_fc1(const float* __restrict__ g1, const float* __restrict__ be1,
                      const float* __restrict__ Wf1, const float* __restrict__ bf1) {
    __shared__ float a[128];
    int g = blockIdx.x, j = threadIdx.x;
    float xv = g_xgp[g*NINVc + j];
    a[j] = elu1((xv - g_mean1[j]) * g_rstd1[j] * g1[j] + be1[j]);
    __syncthreads();
    float acc = bf1[j];
    #pragma unroll 8
    for (int k = 0; k < 128; k++) acc += a[k] * Wf1[k*128 + j];
    g_z1[g*NINVc + j] = acc;
}
__global__ void k_bn2() {
    __shared__ float ssum[256], ssq[256];
    int c = blockIdx.x, tid = threadIdx.x;
    float s = 0.f, q = 0.f;
    for (int g = tid; g < Gc; g += 256) {
        float val = g_z1[g*NINVc + c];
        s += val; q += val*val;
    }
    ssum[tid] = s; ssq[tid] = q; __syncthreads();
    for (int st = 128; st > 0; st >>= 1) {
        if (tid < st) { ssum[tid] += ssum[tid+st]; ssq[tid] += ssq[tid+st]; }
        __syncthreads();
    }
    if (tid == 0) {
        float m = ssum[0] / (float)Gc;
        float var = ssq[0] / (float)Gc - m*m;
        g_mean2[c] = m;
        g_rstd2[c] = rsqrtf(var + 1e-5f);
    }
}
__global__ void k_head(const float* __restrict__ g2, const float* __restrict__ be2,
                       const float* __restrict__ Wf2, const float* __restrict__ bf2,
                       float* __restrict__ out) {
    int w = threadIdx.x >> 5, lane = threadIdx.x & 31;
    int g = blockIdx.x*4 + w;
    if (g >= Gc) return;
    float p = 0.f;
    for (int k = lane; k < 128; k += 32) {
        float zv = g_z1[g*NINVc + k];
        float av = elu1((zv - g_mean2[k]) * g_rstd2[k] * g2[k] + be2[k]);
        p += av * Wf2[k];
    }
    #pragma unroll
    for (int off = 16; off; off >>= 1) p += __shfl_down_sync(0xffffffffu, p, off);
    if (lane == 0) out[g] = p + bf2[0];
}

// ---------------- launch ----------------
extern "C" void kernel_launch(void* const* d_in, const int* in_sizes, int n_in,
                              void* d_out, int out_size) {
    const float* x     = (const float*)d_in[0];
    const float* pos   = (const float*)d_in[1];
    const int*   ei    = (const int*)d_in[2];     // int32 (JAX x64 disabled)
    const float* eattr = (const float*)d_in[3];
    const int*   batch = (const int*)d_in[4];     // int32
    const float* W_es  = (const float*)d_in[5];
    const float* b_es  = (const float*)d_in[6];
    const float* W_ev  = (const float*)d_in[7];
    const float* W1    = (const float*)d_in[8];
    const float* b1    = (const float*)d_in[9];
    const float* W2    = (const float*)d_in[10];
    const float* b2    = (const float*)d_in[11];
    const float* Ws    = (const float*)d_in[12];
    const float* Wv    = (const float*)d_in[13];
    const float* W_inv = (const float*)d_in[14];
    const float* b_inv = (const float*)d_in[15];
    const float* g1    = (const float*)d_in[16];
    const float* be1   = (const float*)d_in[17];
    const float* Wf1   = (const float*)d_in[18];
    const float* bf1   = (const float*)d_in[19];
    const float* g2    = (const float*)d_in[20];
    const float* be2   = (const float*)d_in[21];
    const float* Wf2   = (const float*)d_in[22];
    const float* bf2   = (const float*)d_in[23];
    float* out = (float*)d_out;

    cudaFuncSetAttribute(k_msg_mma, cudaFuncAttributeMaxDynamicSharedMemorySize, TC_SMEM);

    int ztotal = Nn*Ff + Nn + Gc + Gc*NINVc;
    k_zero_embed<<<(ztotal + 255)/256, 256>>>(x, pos, W_es, b_es, W_ev);   // #1
    k_hist<<<(Ee + 255)/256, 256>>>(ei);                                   // #2
    k_scan<<<1, 1024>>>();                                                 // #3
    k_edge_prep<<<(Ee + 255)/256, 256>>>(pos, ei, eattr);                  // #4

    for (int l = 0; l < NLc; l++) {
        k_msg_mma<<<296, 256, TC_SMEM>>>(W1 + l*5*Hc, b1 + l*Hc,
                                         W2 + l*Hc*3*Ff, b2 + l*3*Ff);
        k_update<<<(Nn + 7)/8, 256>>>(Ws + l*Ff*Ff, Wv + l*Ff*Ff, (l < NLc-1) ? 1 : 0);
    }

    k_inv<<<1024, 128>>>(W_inv, b_inv, batch);
    k_pool_bn1<<<NINVc, 256>>>();
    k_fc1<<<Gc, 128>>>(g1, be1, Wf1, bf1);
    k_bn2<<<NINVc, 256>>>();
    k_head<<<Gc/4, 128>>>(g2, be2, Wf2, bf2, out);
}